// round 4
// baseline (speedup 1.0000x reference)
#include <cuda_runtime.h>
#include <cuda_bf16.h>
#include <math.h>
#include <stdint.h>

// ---------------------------------------------------------------------------
// Problem constants
// ---------------------------------------------------------------------------
#define BATCH 8
#define LTOK  4800
#define CDIM  256
#define HEADS 8
#define DHEAD 32
#define NPROT 8
#define NLAYER 4
#define NTOK  (BATCH * LTOK)          // 38400
#define EPS_ATTN 1e-6f
#define EPS_LN   1e-5f

// Output layout (floats), tuple order:
// feat0, feat1, class0, class1, f0p, f1p, prototype
#define OF_F0    0
#define OF_F1    (NTOK * CDIM)
#define OF_C0    (2 * NTOK * CDIM)
#define OF_C1    (OF_C0 + NTOK)
#define OF_F0P   (OF_C1 + NTOK)
#define OF_F1P   (OF_F0P + NTOK * NPROT)
#define OF_PROT  (OF_F1P + NTOK * NPROT)

// ---------------------------------------------------------------------------
// Device scratch (no allocation allowed)
// ---------------------------------------------------------------------------
__device__ __align__(16) float g_q  [NTOK * CDIM];       // q-phi / z
__device__ __align__(16) float g_k  [NTOK * CDIM];       // k-phi / t
__device__ __align__(16) float g_v  [NTOK * CDIM];
__device__ __align__(16) float g_kv [BATCH * NPROT * HEADS * DHEAD * DHEAD];
__device__ __align__(16) float g_ks [BATCH * NPROT * HEADS * DHEAD];
__device__ int   g_cls0[NTOK];
__device__ int   g_cls1[NTOK];
__device__ int   g_list0[BATCH * NPROT * LTOK];
__device__ int   g_list1[BATCH * NPROT * LTOK];
__device__ int   g_cnt0[BATCH * NPROT];
__device__ int   g_cnt1[BATCH * NPROT];

// bf16 hi/lo activation buffers
__device__ __align__(16) __nv_bfloat16 g_x0h[NTOK * CDIM];
__device__ __align__(16) __nv_bfloat16 g_x0l[NTOK * CDIM];
__device__ __align__(16) __nv_bfloat16 g_x1h[NTOK * CDIM];
__device__ __align__(16) __nv_bfloat16 g_x1l[NTOK * CDIM];
__device__ __align__(16) __nv_bfloat16 g_mh [NTOK * CDIM];   // msg, then LN(u)
__device__ __align__(16) __nv_bfloat16 g_ml [NTOK * CDIM];
__device__ __align__(16) __nv_bfloat16 g_hh [NTOK * 2 * CDIM];
__device__ __align__(16) __nv_bfloat16 g_hl [NTOK * 2 * CDIM];

// Transposed+split weights per layer
#define WOFF_Q 0
#define WOFF_K 65536
#define WOFF_V 131072
#define WOFF_M 196608
#define WOFF_1 262144
#define WOFF_2 524288
#define WLSZ   655360
__device__ __align__(16) __nv_bfloat16 g_whi[NLAYER * WLSZ];
__device__ __align__(16) __nv_bfloat16 g_wlo[NLAYER * WLSZ];

// ---------------------------------------------------------------------------
// Helpers
// ---------------------------------------------------------------------------
__device__ __forceinline__ uint32_t smem_u32(const void* p) {
    uint32_t a;
    asm("{ .reg .u64 t; cvta.to.shared.u64 t, %1; cvt.u32.u64 %0, t; }"
        : "=r"(a) : "l"(p));
    return a;
}
__device__ __forceinline__ float warp_sum(float v) {
    #pragma unroll
    for (int o = 16; o; o >>= 1) v += __shfl_xor_sync(0xffffffffu, v, o);
    return v;
}
__device__ __forceinline__ void ldsm4(uint32_t* r, uint32_t addr) {
    asm volatile("ldmatrix.sync.aligned.m8n8.x4.shared.b16 {%0,%1,%2,%3}, [%4];"
                 : "=r"(r[0]), "=r"(r[1]), "=r"(r[2]), "=r"(r[3]) : "r"(addr));
}
__device__ __forceinline__ void mma16816(float* c, const uint32_t* a,
                                         uint32_t b0, uint32_t b1) {
    asm volatile(
        "mma.sync.aligned.m16n8k16.row.col.f32.bf16.bf16.f32 "
        "{%0,%1,%2,%3}, {%4,%5,%6,%7}, {%8,%9}, {%0,%1,%2,%3};"
        : "+f"(c[0]), "+f"(c[1]), "+f"(c[2]), "+f"(c[3])
        : "r"(a[0]), "r"(a[1]), "r"(a[2]), "r"(a[3]), "r"(b0), "r"(b1));
}
__device__ __forceinline__ void cpasync16(uint32_t dst, const __nv_bfloat16* src) {
    asm volatile("cp.async.cg.shared.global [%0], [%1], 16;"
                 :: "r"(dst), "l"(__cvta_generic_to_global(src)));
}
#define CP_COMMIT() asm volatile("cp.async.commit_group;" ::: "memory")

__device__ __forceinline__ void split_store(float v, __nv_bfloat16* ph, __nv_bfloat16* pl) {
    __nv_bfloat16 h = __float2bfloat16(v);
    *ph = h;
    *pl = __float2bfloat16(v - __bfloat162float(h));
}

// ---------------------------------------------------------------------------
// Fully-async mma.sync GEMM: C[M,N] = f(A[M,K] @ W[K,N]), bf16 hi/lo 3-pass.
// A operands pre-split bf16 hi/lo [M,K] row-major (lda elements).
// B operands pre-split bf16 hi/lo [N,K] row-major.
// CTA tile 128x128, K-chunks of 32, 2-stage cp.async pipeline.
// EPI: 0 none, 1 phi=elu+1, 2 relu.
// OUT: 0 fp32 Cf, 1 bf16 hi/lo split (Chi/Clo).
// CONCAT: A covers k<256, A2 covers k>=256 (both lda=256).
// ---------------------------------------------------------------------------
#define RS      40                     // SMEM row stride (bf16) -> 80B
#define SA_HI   0
#define SA_LO   10240
#define SB_HI   20480
#define SB_LO   30720
#define STG_SZ  40960
#define DYN_SMEM (2 * STG_SZ)          // 81920

template <int EPI, int OUT, bool CONCAT>
__global__ __launch_bounds__(256, 2)
void gemm_as(const __nv_bfloat16* __restrict__ Ahi, const __nv_bfloat16* __restrict__ Alo,
             const __nv_bfloat16* __restrict__ A2hi, const __nv_bfloat16* __restrict__ A2lo,
             int lda,
             const __nv_bfloat16* __restrict__ Bhi, const __nv_bfloat16* __restrict__ Blo,
             int K,
             float* __restrict__ Cf, __nv_bfloat16* __restrict__ Chi,
             __nv_bfloat16* __restrict__ Clo, int cstride)
{
    extern __shared__ __align__(128) char sm[];
    const uint32_t sbase = smem_u32(sm);
    const int tid  = threadIdx.x;
    const int lane = tid & 31;
    const int wid  = tid >> 5;
    const int wm   = wid >> 1;         // 0..3 -> M offset wm*32
    const int wn   = wid & 1;          // 0..1 -> N offset wn*64
    const int m0   = blockIdx.y * 128;
    const int n0   = blockIdx.x * 128;
    const int chunks = K >> 5;

    float acc[2][8][4];
    #pragma unroll
    for (int i = 0; i < 2; i++)
        #pragma unroll
        for (int j = 0; j < 8; j++)
            #pragma unroll
            for (int t = 0; t < 4; t++) acc[i][j][t] = 0.f;

    // per-thread cp.async coordinates (row, 16B segment)
    const int car = tid >> 2;          // 0..63 (x2 iters -> 128 rows)
    const int cas = tid & 3;           // 0..3  (seg*8 bf16 = 16B)

    auto issue = [&](int c) {
        const uint32_t stg = sbase + (c & 1) * STG_SZ;
        const int k0 = c * 32;
        const __nv_bfloat16* ah = Ahi;
        const __nv_bfloat16* al = Alo;
        int koff = k0;
        if (CONCAT && k0 >= 256) { ah = A2hi; al = A2lo; koff = k0 - 256; }
        #pragma unroll
        for (int i = 0; i < 2; i++) {
            int row = car + i * 64;
            uint32_t doff = (uint32_t)(row * RS + cas * 8) * 2;
            size_t agoff = (size_t)(m0 + row) * lda + koff + cas * 8;
            cpasync16(stg + SA_HI + doff, ah + agoff);
            cpasync16(stg + SA_LO + doff, al + agoff);
            size_t bgoff = (size_t)(n0 + row) * K + k0 + cas * 8;
            cpasync16(stg + SB_HI + doff, Bhi + bgoff);
            cpasync16(stg + SB_LO + doff, Blo + bgoff);
        }
    };

    issue(0); CP_COMMIT();

    // ldmatrix lane address components
    const int arow = wm * 32 + (lane & 15);
    const int ako  = (lane >> 4) << 3;
    const int brow = wn * 64 + ((lane >> 4) << 3) + (lane & 7);
    const int bko  = ((lane >> 3) & 1) << 3;

    for (int c = 0; c < chunks; c++) {
        const bool more = (c + 1 < chunks);
        if (more) { issue(c + 1); CP_COMMIT(); }
        if (more) asm volatile("cp.async.wait_group 1;" ::: "memory");
        else      asm volatile("cp.async.wait_group 0;" ::: "memory");
        __syncthreads();

        const uint32_t stg = sbase + (c & 1) * STG_SZ;

        #pragma unroll
        for (int ks = 0; ks < 2; ks++) {
            const int ko = ks * 16;
            uint32_t ah[2][4], al[2][4], bf[4][4];
            #pragma unroll
            for (int mt = 0; mt < 2; mt++) {
                uint32_t ad = stg + SA_HI + (uint32_t)((arow + mt * 16) * RS + ko + ako) * 2;
                ldsm4(ah[mt], ad);
                ldsm4(al[mt], ad + (SA_LO - SA_HI));
            }
            #pragma unroll
            for (int g = 0; g < 4; g++) {
                uint32_t bd = stg + SB_HI + (uint32_t)((brow + g * 16) * RS + ko + bko) * 2;
                ldsm4(bf[g], bd);
            }
            #pragma unroll
            for (int mt = 0; mt < 2; mt++)
                #pragma unroll
                for (int g = 0; g < 4; g++) {
                    mma16816(acc[mt][g * 2 + 0], ah[mt], bf[g][0], bf[g][1]);
                    mma16816(acc[mt][g * 2 + 1], ah[mt], bf[g][2], bf[g][3]);
                    mma16816(acc[mt][g * 2 + 0], al[mt], bf[g][0], bf[g][1]);
                    mma16816(acc[mt][g * 2 + 1], al[mt], bf[g][2], bf[g][3]);
                }
            #pragma unroll
            for (int g = 0; g < 4; g++) {
                uint32_t bd = stg + SB_LO + (uint32_t)((brow + g * 16) * RS + ko + bko) * 2;
                ldsm4(bf[g], bd);
            }
            #pragma unroll
            for (int mt = 0; mt < 2; mt++)
                #pragma unroll
                for (int g = 0; g < 4; g++) {
                    mma16816(acc[mt][g * 2 + 0], ah[mt], bf[g][0], bf[g][1]);
                    mma16816(acc[mt][g * 2 + 1], ah[mt], bf[g][2], bf[g][3]);
                }
        }
        __syncthreads();
    }

    // Epilogue
    const int gp = lane >> 2;
    const int tq = lane & 3;
    #pragma unroll
    for (int mt = 0; mt < 2; mt++) {
        #pragma unroll
        for (int nt = 0; nt < 8; nt++) {
            float* cc = acc[mt][nt];
            #pragma unroll
            for (int t = 0; t < 4; t++) {
                float v = cc[t];
                if (EPI == 1) v = (v > 0.f) ? (v + 1.f) : expf(v);
                else if (EPI == 2) v = fmaxf(v, 0.f);
                cc[t] = v;
            }
            size_t row = (size_t)(m0 + wm * 32 + mt * 16 + gp);
            int col = n0 + wn * 64 + nt * 8 + tq * 2;
            if (OUT == 0) {
                *(float2*)(Cf + row * cstride + col)       = make_float2(cc[0], cc[1]);
                *(float2*)(Cf + (row + 8) * cstride + col) = make_float2(cc[2], cc[3]);
            } else {
                #pragma unroll
                for (int rr = 0; rr < 2; rr++) {
                    size_t o = (row + rr * 8) * cstride + col;
                    __nv_bfloat162 hh, ll;
                    float v0 = cc[rr * 2 + 0], v1 = cc[rr * 2 + 1];
                    hh.x = __float2bfloat16(v0);
                    hh.y = __float2bfloat16(v1);
                    ll.x = __float2bfloat16(v0 - __bfloat162float(hh.x));
                    ll.y = __float2bfloat16(v1 - __bfloat162float(hh.y));
                    *(uint32_t*)(Chi + o) = *(uint32_t*)&hh;
                    *(uint32_t*)(Clo + o) = *(uint32_t*)&ll;
                }
            }
        }
    }
}

// ---------------------------------------------------------------------------
// Weight prep: out[n*K + k] = split(W[k*N + n]) into bf16 hi/lo
// ---------------------------------------------------------------------------
__global__ void prep_w(const float* __restrict__ W, int Kd, int Nd,
                       __nv_bfloat16* __restrict__ hi, __nv_bfloat16* __restrict__ lo)
{
    int idx = blockIdx.x * blockDim.x + threadIdx.x;
    if (idx >= Kd * Nd) return;
    int n = idx / Kd;
    int k = idx - n * Kd;
    float w = W[(size_t)k * Nd + n];
    __nv_bfloat16 h = __float2bfloat16(w);
    hi[idx] = h;
    lo[idx] = __float2bfloat16(w - __bfloat162float(h));
}

// ---------------------------------------------------------------------------
// Classification (warp/token)
// ---------------------------------------------------------------------------
__global__ __launch_bounds__(256)
void classify_kernel(const float* __restrict__ fwp, const float* __restrict__ proto,
                     float* __restrict__ out_fp, float* __restrict__ out_clsf,
                     int* __restrict__ cls)
{
    __shared__ float sp[NPROT][CDIM];
    int tid = threadIdx.x;
    #pragma unroll
    for (int i = 0; i < 8; i++) {
        int idx = tid + i * 256;
        sp[idx >> 8][idx & 255] = proto[idx];
    }
    __syncthreads();

    int tok = blockIdx.x * 8 + (tid >> 5);
    int lane = tid & 31;
    const float* f = fwp + (size_t)tok * CDIM;

    float acc[NPROT];
    #pragma unroll
    for (int p = 0; p < NPROT; p++) acc[p] = 0.f;
    #pragma unroll
    for (int i = 0; i < 8; i++) {
        float x = f[lane + i * 32];
        #pragma unroll
        for (int p = 0; p < NPROT; p++) acc[p] += x * sp[p][lane + i * 32];
    }
    #pragma unroll
    for (int p = 0; p < NPROT; p++) acc[p] = warp_sum(acc[p]);

    if (lane < NPROT) out_fp[(size_t)tok * NPROT + lane] = acc[lane];
    if (lane == 0) {
        int best = 0; float bv = acc[0];
        #pragma unroll
        for (int p = 1; p < NPROT; p++) if (acc[p] > bv) { bv = acc[p]; best = p; }
        cls[tok] = best;
        out_clsf[tok] = (float)best;
    }
}

// ---------------------------------------------------------------------------
// Token list build (ballot compaction), 32 thr/block
// ---------------------------------------------------------------------------
__global__ void build_list(const int* __restrict__ cls, const int* __restrict__ mask,
                           int* __restrict__ list, int* __restrict__ cnt)
{
    int g = blockIdx.x;              // b*8 + c
    int b = g >> 3, c = g & 7;
    int lane = threadIdx.x;
    const int* cb = cls + b * LTOK;
    const int* mb = mask + b * LTOK;
    int base = g * LTOK;
    int count = 0;
    for (int s0 = 0; s0 < LTOK; s0 += 32) {
        int s = s0 + lane;
        bool hit = (cb[s] == c) && (mb[s] != 0);
        unsigned m = __ballot_sync(0xffffffffu, hit);
        if (hit) list[base + count + __popc(m & ((1u << lane) - 1u))] = s;
        count += __popc(m);
    }
    if (lane == 0) cnt[g] = count;
}

// ---------------------------------------------------------------------------
// Per-class stats via token lists. Block per (b,c,h).
// ---------------------------------------------------------------------------
__global__ __launch_bounds__(256)
void stats_kernel(const float* __restrict__ K_, const float* __restrict__ V_,
                  const int* __restrict__ list, const int* __restrict__ cnt,
                  float* __restrict__ KV, float* __restrict__ KS)
{
    __shared__ float sk[32][33];
    __shared__ float sv[32][33];
    __shared__ int   st[32];

    int bid = blockIdx.x;
    int h = bid & 7;
    int c = (bid >> 3) & 7;
    int b = bid >> 6;
    int g = b * 8 + c;

    int tid = threadIdx.x;
    int d  = tid >> 3;
    int e0 = (tid & 7) * 4;

    float a0 = 0.f, a1 = 0.f, a2 = 0.f, a3 = 0.f;
    float ssum = 0.f;

    const float* Kb = K_ + (size_t)b * LTOK * CDIM + h * DHEAD;
    const float* Vb = V_ + (size_t)b * LTOK * CDIM + h * DHEAD;
    int n = cnt[g];
    int base = g * LTOK;

    for (int i0 = 0; i0 < n; i0 += 32) {
        if (tid < 32) st[tid] = (i0 + tid < n) ? list[base + i0 + tid] : -1;
        __syncthreads();
        #pragma unroll
        for (int i = 0; i < 4; i++) {
            int idx = tid + i * 256;
            int s = idx >> 5;
            int dd = idx & 31;
            int t = st[s];
            float kk = 0.f, vv = 0.f;
            if (t >= 0) {
                kk = Kb[(size_t)t * CDIM + dd];
                vv = Vb[(size_t)t * CDIM + dd];
            }
            sk[s][dd] = kk;
            sv[s][dd] = vv;
        }
        __syncthreads();
        #pragma unroll
        for (int s = 0; s < 32; s++) {
            float kd = sk[s][d];
            a0 += kd * sv[s][e0 + 0];
            a1 += kd * sv[s][e0 + 1];
            a2 += kd * sv[s][e0 + 2];
            a3 += kd * sv[s][e0 + 3];
        }
        if (tid < 32) {
            #pragma unroll
            for (int s = 0; s < 32; s++) ssum += sk[s][tid];
        }
        __syncthreads();
    }

    size_t o = ((((size_t)b * NPROT + c) * HEADS + h) * DHEAD + d) * DHEAD + e0;
    KV[o + 0] = a0; KV[o + 1] = a1; KV[o + 2] = a2; KV[o + 3] = a3;
    if (tid < 32) KS[(((size_t)b * NPROT + c) * HEADS + h) * DHEAD + tid] = ssum;
}

// ---------------------------------------------------------------------------
// Apply: block per (b,c); kv/ks in SMEM; warp/token; writes msg hi/lo bf16.
// ---------------------------------------------------------------------------
__global__ __launch_bounds__(256)
void apply_kernel(const float* __restrict__ Q, const float* __restrict__ KV,
                  const float* __restrict__ KS, const int* __restrict__ list,
                  const int* __restrict__ cnt,
                  __nv_bfloat16* __restrict__ MH, __nv_bfloat16* __restrict__ ML)
{
    __shared__ float skv[HEADS][DHEAD][DHEAD];
    __shared__ float sks[HEADS][DHEAD];

    int g = blockIdx.x;              // b*8 + c
    int b = g >> 3;
    int tid = threadIdx.x;
    int w = tid >> 5, lane = tid & 31;

    for (int i = tid; i < HEADS * DHEAD * DHEAD; i += 256)
        skv[i >> 10][(i >> 5) & 31][i & 31] = KV[(size_t)g * HEADS * DHEAD * DHEAD + i];
    for (int i = tid; i < HEADS * DHEAD; i += 256)
        sks[i >> 5][i & 31] = KS[(size_t)g * HEADS * DHEAD + i];
    __syncthreads();

    int n = cnt[g];
    int base = g * LTOK;

    for (int i0 = 0; i0 < n; i0 += 8) {
        int ii = i0 + w;
        if (ii < n) {
            int t = list[base + ii];
            size_t roff = ((size_t)b * LTOK + t) * CDIM;
            const float* qrow = Q + roff;
            #pragma unroll
            for (int h = 0; h < HEADS; h++) {
                float qd = qrow[h * 32 + lane];
                float den = warp_sum(qd * sks[h][lane]) + EPS_ATTN;
                float num = 0.f;
                #pragma unroll
                for (int dd = 0; dd < 32; dd++)
                    num += __shfl_sync(0xffffffffu, qd, dd) * skv[h][dd][lane];
                float m = num / den;
                split_store(m, MH + roff + h * 32 + lane, ML + roff + h * 32 + lane);
            }
        }
    }
}

// ---------------------------------------------------------------------------
// LayerNorm: reads fp32, writes bf16 hi/lo (warp/token)
// ---------------------------------------------------------------------------
__global__ __launch_bounds__(256)
void ln_kernel(const float* __restrict__ X, const float* __restrict__ g,
               const float* __restrict__ b,
               __nv_bfloat16* __restrict__ YH, __nv_bfloat16* __restrict__ YL)
{
    int tok = blockIdx.x * 8 + (threadIdx.x >> 5);
    int lane = threadIdx.x & 31;
    const float* x = X + (size_t)tok * CDIM;
    float v[8], s = 0.f;
    #pragma unroll
    for (int i = 0; i < 8; i++) { v[i] = x[i * 32 + lane]; s += v[i]; }
    float mean = warp_sum(s) * (1.f / 256.f);
    float s2 = 0.f;
    #pragma unroll
    for (int i = 0; i < 8; i++) { float dd = v[i] - mean; s2 += dd * dd; }
    float rs = rsqrtf(warp_sum(s2) * (1.f / 256.f) + EPS_LN);
    size_t roff = (size_t)tok * CDIM;
    #pragma unroll
    for (int i = 0; i < 8; i++) {
        int cc = i * 32 + lane;
        float y = (v[i] - mean) * rs * g[cc] + b[cc];
        split_store(y, YH + roff + cc, YL + roff + cc);
    }
}

// ---------------------------------------------------------------------------
// Final: x += LN(z)*g2+b2 at valid tokens; refresh x hi/lo.
// ---------------------------------------------------------------------------
__global__ __launch_bounds__(256)
void final_kernel(const float* __restrict__ Z, const float* __restrict__ g,
                  const float* __restrict__ b, const int* __restrict__ mask,
                  float* __restrict__ X,
                  __nv_bfloat16* __restrict__ XH, __nv_bfloat16* __restrict__ XL)
{
    int tok = blockIdx.x * 8 + (threadIdx.x >> 5);
    int lane = threadIdx.x & 31;
    if (mask[tok] == 0) return;
    const float* z = Z + (size_t)tok * CDIM;
    float v[8], s = 0.f;
    #pragma unroll
    for (int i = 0; i < 8; i++) { v[i] = z[i * 32 + lane]; s += v[i]; }
    float mean = warp_sum(s) * (1.f / 256.f);
    float s2 = 0.f;
    #pragma unroll
    for (int i = 0; i < 8; i++) { float dd = v[i] - mean; s2 += dd * dd; }
    float rs = rsqrtf(warp_sum(s2) * (1.f / 256.f) + EPS_LN);
    size_t roff = (size_t)tok * CDIM;
    float* x = X + roff;
    #pragma unroll
    for (int i = 0; i < 8; i++) {
        int cc = i * 32 + lane;
        float xn = x[cc] + (v[i] - mean) * rs * g[cc] + b[cc];
        x[cc] = xn;
        split_store(xn, XH + roff + cc, XL + roff + cc);
    }
}

// ---------------------------------------------------------------------------
// Copy + split init
// ---------------------------------------------------------------------------
__global__ void copy_split_kernel(const float* __restrict__ s, float* __restrict__ d,
                                  __nv_bfloat16* __restrict__ dh,
                                  __nv_bfloat16* __restrict__ dl, int n)
{
    int i = blockIdx.x * blockDim.x + threadIdx.x;
    int stride = gridDim.x * blockDim.x;
    for (; i < n; i += stride) {
        float v = s[i];
        d[i] = v;
        split_store(v, dh + i, dl + i);
    }
}
__global__ void copy_kernel(const float* __restrict__ s, float* __restrict__ d, int n)
{
    int i = blockIdx.x * blockDim.x + threadIdx.x;
    int stride = gridDim.x * blockDim.x;
    for (; i < n; i += stride) d[i] = s[i];
}

// ---------------------------------------------------------------------------
// Host orchestration
// ---------------------------------------------------------------------------
struct Bufs {
    float *q, *k, *v, *kv, *ks;
    __nv_bfloat16 *mh, *ml, *hh, *hl;
};

static void run_layer(float* x, __nv_bfloat16* xh, __nv_bfloat16* xl,
                      const __nv_bfloat16* sh, const __nv_bfloat16* sl,
                      const int* listx, const int* cntx,
                      const int* listsrc, const int* cntsrc,
                      const int* maskx,
                      const __nv_bfloat16* whi, const __nv_bfloat16* wlo,
                      const float* gg1, const float* bb1,
                      const float* gg2, const float* bb2,
                      const Bufs& B)
{
    dim3 blk(256);
    dim3 gN256(2, NTOK / 128);
    dim3 gN512(4, NTOK / 128);

    gemm_as<1, 0, false><<<gN256, blk, DYN_SMEM>>>(xh, xl, nullptr, nullptr, CDIM,
        whi + WOFF_Q, wlo + WOFF_Q, 256, B.q, nullptr, nullptr, CDIM);
    gemm_as<1, 0, false><<<gN256, blk, DYN_SMEM>>>(sh, sl, nullptr, nullptr, CDIM,
        whi + WOFF_K, wlo + WOFF_K, 256, B.k, nullptr, nullptr, CDIM);
    gemm_as<0, 0, false><<<gN256, blk, DYN_SMEM>>>(sh, sl, nullptr, nullptr, CDIM,
        whi + WOFF_V, wlo + WOFF_V, 256, B.v, nullptr, nullptr, CDIM);

    stats_kernel<<<BATCH * NPROT * HEADS, blk>>>(B.k, B.v, listsrc, cntsrc, B.kv, B.ks);
    apply_kernel<<<BATCH * NPROT, blk>>>(B.q, B.kv, B.ks, listx, cntx, B.mh, B.ml);

    gemm_as<0, 0, false><<<gN256, blk, DYN_SMEM>>>(B.mh, B.ml, nullptr, nullptr, CDIM,
        whi + WOFF_M, wlo + WOFF_M, 256, B.k, nullptr, nullptr, CDIM);   // t
    ln_kernel<<<NTOK / 8, blk>>>(B.k, gg1, bb1, B.mh, B.ml);             // u (reuse msg)

    gemm_as<2, 1, true ><<<gN512, blk, DYN_SMEM>>>(xh, xl, B.mh, B.ml, CDIM,
        whi + WOFF_1, wlo + WOFF_1, 512, nullptr, B.hh, B.hl, 2 * CDIM);
    gemm_as<0, 0, false><<<gN256, blk, DYN_SMEM>>>(B.hh, B.hl, nullptr, nullptr, 2 * CDIM,
        whi + WOFF_2, wlo + WOFF_2, 512, B.q, nullptr, nullptr, CDIM);   // z
    final_kernel<<<NTOK / 8, blk>>>(B.q, gg2, bb2, maskx, x, xh, xl);
}

extern "C" void kernel_launch(void* const* d_in, const int* in_sizes, int n_in,
                              void* d_out, int out_size)
{
    const float* feat0 = (const float*)d_in[0];
    const float* feat1 = (const float*)d_in[1];
    const int*   mask0 = (const int*)  d_in[2];
    const int*   mask1 = (const int*)  d_in[3];
    const float* f0wp  = (const float*)d_in[4];
    const float* f1wp  = (const float*)d_in[5];
    const float* proto = (const float*)d_in[6];
    const float* Wq    = (const float*)d_in[7];
    const float* Wk    = (const float*)d_in[8];
    const float* Wv    = (const float*)d_in[9];
    const float* Wm    = (const float*)d_in[10];
    const float* W1    = (const float*)d_in[11];
    const float* W2    = (const float*)d_in[12];
    const float* G1    = (const float*)d_in[13];
    const float* B1    = (const float*)d_in[14];
    const float* G2    = (const float*)d_in[15];
    const float* B2    = (const float*)d_in[16];

    cudaFuncSetAttribute(gemm_as<0, 0, false>, cudaFuncAttributeMaxDynamicSharedMemorySize, DYN_SMEM);
    cudaFuncSetAttribute(gemm_as<1, 0, false>, cudaFuncAttributeMaxDynamicSharedMemorySize, DYN_SMEM);
    cudaFuncSetAttribute(gemm_as<2, 1, true >, cudaFuncAttributeMaxDynamicSharedMemorySize, DYN_SMEM);

    float* out = (float*)d_out;
    float* x0     = out + OF_F0;
    float* x1     = out + OF_F1;
    float* cls0f  = out + OF_C0;
    float* cls1f  = out + OF_C1;
    float* f0p    = out + OF_F0P;
    float* f1p    = out + OF_F1P;
    float* protoO = out + OF_PROT;

    Bufs B;
    int *c0, *c1, *l0, *l1, *n0, *n1;
    __nv_bfloat16 *whi, *wlo, *x0h, *x0l, *x1h, *x1l;
    cudaGetSymbolAddress((void**)&B.q,  g_q);
    cudaGetSymbolAddress((void**)&B.k,  g_k);
    cudaGetSymbolAddress((void**)&B.v,  g_v);
    cudaGetSymbolAddress((void**)&B.kv, g_kv);
    cudaGetSymbolAddress((void**)&B.ks, g_ks);
    cudaGetSymbolAddress((void**)&B.mh, g_mh);
    cudaGetSymbolAddress((void**)&B.ml, g_ml);
    cudaGetSymbolAddress((void**)&B.hh, g_hh);
    cudaGetSymbolAddress((void**)&B.hl, g_hl);
    cudaGetSymbolAddress((void**)&c0,  g_cls0);
    cudaGetSymbolAddress((void**)&c1,  g_cls1);
    cudaGetSymbolAddress((void**)&l0,  g_list0);
    cudaGetSymbolAddress((void**)&l1,  g_list1);
    cudaGetSymbolAddress((void**)&n0,  g_cnt0);
    cudaGetSymbolAddress((void**)&n1,  g_cnt1);
    cudaGetSymbolAddress((void**)&whi, g_whi);
    cudaGetSymbolAddress((void**)&wlo, g_wlo);
    cudaGetSymbolAddress((void**)&x0h, g_x0h);
    cudaGetSymbolAddress((void**)&x0l, g_x0l);
    cudaGetSymbolAddress((void**)&x1h, g_x1h);
    cudaGetSymbolAddress((void**)&x1l, g_x1l);

    // Init: features into output buffer + bf16 hi/lo working copies.
    copy_split_kernel<<<2048, 256>>>(feat0, x0, x0h, x0l, NTOK * CDIM);
    copy_split_kernel<<<2048, 256>>>(feat1, x1, x1h, x1l, NTOK * CDIM);
    copy_kernel<<<8, 256>>>(proto, protoO, NPROT * CDIM);

    classify_kernel<<<NTOK / 8, 256>>>(f0wp, proto, f0p, cls0f, c0);
    classify_kernel<<<NTOK / 8, 256>>>(f1wp, proto, f1p, cls1f, c1);
    build_list<<<BATCH * NPROT, 32>>>(c0, mask0, l0, n0);
    build_list<<<BATCH * NPROT, 32>>>(c1, mask1, l1, n1);

    // Weight prep (transpose + hi/lo split), all layers.
    for (int i = 0; i < NLAYER; i++) {
        __nv_bfloat16* hb = whi + (size_t)i * WLSZ;
        __nv_bfloat16* lb = wlo + (size_t)i * WLSZ;
        prep_w<<<(65536 + 255) / 256, 256>>>(Wq + (size_t)i * 65536, 256, 256, hb + WOFF_Q, lb + WOFF_Q);
        prep_w<<<(65536 + 255) / 256, 256>>>(Wk + (size_t)i * 65536, 256, 256, hb + WOFF_K, lb + WOFF_K);
        prep_w<<<(65536 + 255) / 256, 256>>>(Wv + (size_t)i * 65536, 256, 256, hb + WOFF_V, lb + WOFF_V);
        prep_w<<<(65536 + 255) / 256, 256>>>(Wm + (size_t)i * 65536, 256, 256, hb + WOFF_M, lb + WOFF_M);
        prep_w<<<(262144 + 255) / 256, 256>>>(W1 + (size_t)i * 262144, 512, 512, hb + WOFF_1, lb + WOFF_1);
        prep_w<<<(131072 + 255) / 256, 256>>>(W2 + (size_t)i * 131072, 512, 256, hb + WOFF_2, lb + WOFF_2);
    }

    for (int i = 0; i < NLAYER; i++) {
        const __nv_bfloat16* hb = whi + (size_t)i * WLSZ;
        const __nv_bfloat16* lb = wlo + (size_t)i * WLSZ;
        const float* gg1 = G1 + (size_t)i * CDIM;
        const float* bb1 = B1 + (size_t)i * CDIM;
        const float* gg2 = G2 + (size_t)i * CDIM;
        const float* bb2 = B2 + (size_t)i * CDIM;

        if ((i & 1) == 0) {  // self-self
            run_layer(x0, x0h, x0l, x0h, x0l, l0, n0, l0, n0, mask0,
                      hb, lb, gg1, bb1, gg2, bb2, B);
            run_layer(x1, x1h, x1l, x1h, x1l, l1, n1, l1, n1, mask1,
                      hb, lb, gg1, bb1, gg2, bb2, B);
        } else {             // cross-self: feat0 attends feat1, then feat1 attends UPDATED feat0
            run_layer(x0, x0h, x0l, x1h, x1l, l0, n0, l1, n1, mask0,
                      hb, lb, gg1, bb1, gg2, bb2, B);
            run_layer(x1, x1h, x1l, x0h, x0l, l1, n1, l0, n0, mask1,
                      hb, lb, gg1, bb1, gg2, bb2, B);
        }
    }
    (void)in_sizes; (void)n_in; (void)out_size;
}

// round 5
// speedup vs baseline: 1.1486x; 1.1486x over previous
#include <cuda_runtime.h>
#include <cuda_fp16.h>
#include <math.h>
#include <stdint.h>

// ---------------------------------------------------------------------------
// Problem constants
// ---------------------------------------------------------------------------
#define BATCH 8
#define LTOK  4800
#define CDIM  256
#define HEADS 8
#define DHEAD 32
#define NPROT 8
#define NLAYER 4
#define NTOK  (BATCH * LTOK)          // 38400
#define EPS_ATTN 1e-6f
#define EPS_LN   1e-5f

// Output layout (floats), tuple order:
// feat0, feat1, class0, class1, f0p, f1p, prototype
#define OF_F0    0
#define OF_F1    (NTOK * CDIM)
#define OF_C0    (2 * NTOK * CDIM)
#define OF_C1    (OF_C0 + NTOK)
#define OF_F0P   (OF_C1 + NTOK)
#define OF_F1P   (OF_F0P + NTOK * NPROT)
#define OF_PROT  (OF_F1P + NTOK * NPROT)

// ---------------------------------------------------------------------------
// Device scratch (no allocation allowed)
// ---------------------------------------------------------------------------
__device__ __align__(16) float g_q  [NTOK * CDIM];       // q-phi / z
__device__ __align__(16) float g_k  [NTOK * CDIM];       // k-phi / t
__device__ __align__(16) float g_v  [NTOK * CDIM];
__device__ __align__(16) float g_kv [BATCH * NPROT * HEADS * DHEAD * DHEAD];
__device__ __align__(16) float g_ks [BATCH * NPROT * HEADS * DHEAD];
__device__ int   g_cls0[NTOK];
__device__ int   g_cls1[NTOK];
__device__ int   g_list0[BATCH * NPROT * LTOK];
__device__ int   g_list1[BATCH * NPROT * LTOK];
__device__ int   g_cnt0[BATCH * NPROT];
__device__ int   g_cnt1[BATCH * NPROT];

// fp16 hi/lo activation buffers
__device__ __align__(16) __half g_x0h[NTOK * CDIM];
__device__ __align__(16) __half g_x0l[NTOK * CDIM];
__device__ __align__(16) __half g_x1h[NTOK * CDIM];
__device__ __align__(16) __half g_x1l[NTOK * CDIM];
__device__ __align__(16) __half g_mh [NTOK * CDIM];   // msg, then LN(u)
__device__ __align__(16) __half g_ml [NTOK * CDIM];
__device__ __align__(16) __half g_hh [NTOK * 2 * CDIM];
__device__ __align__(16) __half g_hl [NTOK * 2 * CDIM];

// Transposed fp16 weights per layer (single fp16; activation carries hi/lo)
#define WOFF_Q 0
#define WOFF_K 65536
#define WOFF_V 131072
#define WOFF_M 196608
#define WOFF_1 262144
#define WOFF_2 524288
#define WLSZ   655360
__device__ __align__(16) __half g_wh[NLAYER * WLSZ];

// ---------------------------------------------------------------------------
// Helpers
// ---------------------------------------------------------------------------
__device__ __forceinline__ uint32_t smem_u32(const void* p) {
    uint32_t a;
    asm("{ .reg .u64 t; cvta.to.shared.u64 t, %1; cvt.u32.u64 %0, t; }"
        : "=r"(a) : "l"(p));
    return a;
}
__device__ __forceinline__ float warp_sum(float v) {
    #pragma unroll
    for (int o = 16; o; o >>= 1) v += __shfl_xor_sync(0xffffffffu, v, o);
    return v;
}
__device__ __forceinline__ void ldsm4(uint32_t* r, uint32_t addr) {
    asm volatile("ldmatrix.sync.aligned.m8n8.x4.shared.b16 {%0,%1,%2,%3}, [%4];"
                 : "=r"(r[0]), "=r"(r[1]), "=r"(r[2]), "=r"(r[3]) : "r"(addr));
}
__device__ __forceinline__ void mma16816(float* c, const uint32_t* a,
                                         uint32_t b0, uint32_t b1) {
    asm volatile(
        "mma.sync.aligned.m16n8k16.row.col.f32.f16.f16.f32 "
        "{%0,%1,%2,%3}, {%4,%5,%6,%7}, {%8,%9}, {%0,%1,%2,%3};"
        : "+f"(c[0]), "+f"(c[1]), "+f"(c[2]), "+f"(c[3])
        : "r"(a[0]), "r"(a[1]), "r"(a[2]), "r"(a[3]), "r"(b0), "r"(b1));
}
__device__ __forceinline__ void cpasync16(uint32_t dst, const __half* src) {
    asm volatile("cp.async.cg.shared.global [%0], [%1], 16;"
                 :: "r"(dst), "l"(__cvta_generic_to_global(src)));
}
#define CP_COMMIT() asm volatile("cp.async.commit_group;" ::: "memory")

__device__ __forceinline__ void split_store(float v, __half* ph, __half* pl) {
    __half h = __float2half(v);
    *ph = h;
    *pl = __float2half(v - __half2float(h));
}

// ---------------------------------------------------------------------------
// mma.sync GEMM: C[M,N] = f(A[M,K] @ W[K,N]), fp16 hi/lo 2-pass
// (A = Ahi + Alo exactly; W rounded to fp16 -> err ~2^-12 per product).
// A pre-split fp16 hi/lo [M,K] row-major; B fp16 [N,K] row-major.
// CTA tile 128x128, K-chunks of 32, 3-stage cp.async pipeline.
// EPI: 0 none, 1 phi=elu+1, 2 relu.  OUT: 0 fp32, 1 fp16 hi/lo split.
// CONCAT: A covers k<256, A2 covers k>=256 (both lda=256).
// ---------------------------------------------------------------------------
#define RS      40                     // SMEM row stride (fp16) -> 80B
#define SA_HI   0
#define SA_LO   10240
#define SB_HI   20480
#define STG_SZ  30720
#define NSTAGE  3
#define DYN_SMEM (NSTAGE * STG_SZ)     // 92160

template <int EPI, int OUT, bool CONCAT>
__global__ __launch_bounds__(256, 2)
void gemm_as(const __half* __restrict__ Ahi, const __half* __restrict__ Alo,
             const __half* __restrict__ A2hi, const __half* __restrict__ A2lo,
             int lda,
             const __half* __restrict__ Bh,
             int K,
             float* __restrict__ Cf, __half* __restrict__ Chi,
             __half* __restrict__ Clo, int cstride)
{
    extern __shared__ __align__(128) char sm[];
    const uint32_t sbase = smem_u32(sm);
    const int tid  = threadIdx.x;
    const int lane = tid & 31;
    const int wid  = tid >> 5;
    const int wm   = wid >> 1;         // 0..3 -> M offset wm*32
    const int wn   = wid & 1;          // 0..1 -> N offset wn*64
    const int m0   = blockIdx.y * 128;
    const int n0   = blockIdx.x * 128;
    const int chunks = K >> 5;

    float acc[2][8][4];
    #pragma unroll
    for (int i = 0; i < 2; i++)
        #pragma unroll
        for (int j = 0; j < 8; j++)
            #pragma unroll
            for (int t = 0; t < 4; t++) acc[i][j][t] = 0.f;

    // per-thread cp.async coordinates
    const int car = tid >> 2;          // 0..63 (x2 iters -> 128 rows)
    const int cas = tid & 3;           // seg*8 fp16 = 16B

    auto issue = [&](int c) {
        const uint32_t stg = sbase + (c % NSTAGE) * STG_SZ;
        const int k0 = c * 32;
        const __half* ah = Ahi;
        const __half* al = Alo;
        int koff = k0;
        if (CONCAT && k0 >= 256) { ah = A2hi; al = A2lo; koff = k0 - 256; }
        #pragma unroll
        for (int i = 0; i < 2; i++) {
            int row = car + i * 64;
            uint32_t doff = (uint32_t)(row * RS + cas * 8) * 2;
            size_t agoff = (size_t)(m0 + row) * lda + koff + cas * 8;
            cpasync16(stg + SA_HI + doff, ah + agoff);
            cpasync16(stg + SA_LO + doff, al + agoff);
            size_t bgoff = (size_t)(n0 + row) * K + k0 + cas * 8;
            cpasync16(stg + SB_HI + doff, Bh + bgoff);
        }
    };

    issue(0); CP_COMMIT();
    if (chunks > 1) { issue(1); CP_COMMIT(); }

    // ldmatrix lane address components
    const int arow = wm * 32 + (lane & 15);
    const int ako  = (lane >> 4) << 3;
    const int brow = wn * 64 + ((lane >> 4) << 3) + (lane & 7);
    const int bko  = ((lane >> 3) & 1) << 3;

    for (int c = 0; c < chunks; c++) {
        if (c + 2 < chunks) {
            issue(c + 2); CP_COMMIT();
            asm volatile("cp.async.wait_group 2;" ::: "memory");
        } else if (c + 1 < chunks) {
            asm volatile("cp.async.wait_group 1;" ::: "memory");
        } else {
            asm volatile("cp.async.wait_group 0;" ::: "memory");
        }
        __syncthreads();

        const uint32_t stg = sbase + (c % NSTAGE) * STG_SZ;

        #pragma unroll
        for (int ks = 0; ks < 2; ks++) {
            const int ko = ks * 16;
            uint32_t ah[2][4], al[2][4], bf[4][4];
            #pragma unroll
            for (int mt = 0; mt < 2; mt++) {
                uint32_t ad = stg + SA_HI + (uint32_t)((arow + mt * 16) * RS + ko + ako) * 2;
                ldsm4(ah[mt], ad);
                ldsm4(al[mt], ad + (SA_LO - SA_HI));
            }
            #pragma unroll
            for (int g = 0; g < 4; g++) {
                uint32_t bd = stg + SB_HI + (uint32_t)((brow + g * 16) * RS + ko + bko) * 2;
                ldsm4(bf[g], bd);
            }
            #pragma unroll
            for (int mt = 0; mt < 2; mt++)
                #pragma unroll
                for (int g = 0; g < 4; g++) {
                    mma16816(acc[mt][g * 2 + 0], ah[mt], bf[g][0], bf[g][1]);
                    mma16816(acc[mt][g * 2 + 1], ah[mt], bf[g][2], bf[g][3]);
                    mma16816(acc[mt][g * 2 + 0], al[mt], bf[g][0], bf[g][1]);
                    mma16816(acc[mt][g * 2 + 1], al[mt], bf[g][2], bf[g][3]);
                }
        }
        __syncthreads();
    }

    // Epilogue
    const int gp = lane >> 2;
    const int tq = lane & 3;
    #pragma unroll
    for (int mt = 0; mt < 2; mt++) {
        #pragma unroll
        for (int nt = 0; nt < 8; nt++) {
            float* cc = acc[mt][nt];
            #pragma unroll
            for (int t = 0; t < 4; t++) {
                float v = cc[t];
                if (EPI == 1) v = (v > 0.f) ? (v + 1.f) : expf(v);
                else if (EPI == 2) v = fmaxf(v, 0.f);
                cc[t] = v;
            }
            size_t row = (size_t)(m0 + wm * 32 + mt * 16 + gp);
            int col = n0 + wn * 64 + nt * 8 + tq * 2;
            if (OUT == 0) {
                *(float2*)(Cf + row * cstride + col)       = make_float2(cc[0], cc[1]);
                *(float2*)(Cf + (row + 8) * cstride + col) = make_float2(cc[2], cc[3]);
            } else {
                #pragma unroll
                for (int rr = 0; rr < 2; rr++) {
                    size_t o = (row + rr * 8) * cstride + col;
                    float v0 = cc[rr * 2 + 0], v1 = cc[rr * 2 + 1];
                    __half h0 = __float2half(v0);
                    __half h1 = __float2half(v1);
                    __half2 hh = __halves2half2(h0, h1);
                    __half2 ll = __halves2half2(
                        __float2half(v0 - __half2float(h0)),
                        __float2half(v1 - __half2float(h1)));
                    *(uint32_t*)(Chi + o) = *(uint32_t*)&hh;
                    *(uint32_t*)(Clo + o) = *(uint32_t*)&ll;
                }
            }
        }
    }
}

// ---------------------------------------------------------------------------
// Weight prep: out[n*K + k] = fp16(W[k*N + n])
// ---------------------------------------------------------------------------
__global__ void prep_w(const float* __restrict__ W, int Kd, int Nd,
                       __half* __restrict__ hi)
{
    int idx = blockIdx.x * blockDim.x + threadIdx.x;
    if (idx >= Kd * Nd) return;
    int n = idx / Kd;
    int k = idx - n * Kd;
    hi[idx] = __float2half(W[(size_t)k * Nd + n]);
}

// ---------------------------------------------------------------------------
// Classification (warp/token)
// ---------------------------------------------------------------------------
__global__ __launch_bounds__(256)
void classify_kernel(const float* __restrict__ fwp, const float* __restrict__ proto,
                     float* __restrict__ out_fp, float* __restrict__ out_clsf,
                     int* __restrict__ cls)
{
    __shared__ float sp[NPROT][CDIM];
    int tid = threadIdx.x;
    #pragma unroll
    for (int i = 0; i < 8; i++) {
        int idx = tid + i * 256;
        sp[idx >> 8][idx & 255] = proto[idx];
    }
    __syncthreads();

    int tok = blockIdx.x * 8 + (tid >> 5);
    int lane = tid & 31;
    const float* f = fwp + (size_t)tok * CDIM;

    float acc[NPROT];
    #pragma unroll
    for (int p = 0; p < NPROT; p++) acc[p] = 0.f;
    #pragma unroll
    for (int i = 0; i < 8; i++) {
        float x = f[lane + i * 32];
        #pragma unroll
        for (int p = 0; p < NPROT; p++) acc[p] += x * sp[p][lane + i * 32];
    }
    #pragma unroll
    for (int p = 0; p < NPROT; p++) acc[p] = warp_sum(acc[p]);

    if (lane < NPROT) out_fp[(size_t)tok * NPROT + lane] = acc[lane];
    if (lane == 0) {
        int best = 0; float bv = acc[0];
        #pragma unroll
        for (int p = 1; p < NPROT; p++) if (acc[p] > bv) { bv = acc[p]; best = p; }
        cls[tok] = best;
        out_clsf[tok] = (float)best;
    }
}

// ---------------------------------------------------------------------------
// Token list build (ballot compaction), 32 thr/block
// ---------------------------------------------------------------------------
__global__ void build_list(const int* __restrict__ cls, const int* __restrict__ mask,
                           int* __restrict__ list, int* __restrict__ cnt)
{
    int g = blockIdx.x;              // b*8 + c
    int b = g >> 3, c = g & 7;
    int lane = threadIdx.x;
    const int* cb = cls + b * LTOK;
    const int* mb = mask + b * LTOK;
    int base = g * LTOK;
    int count = 0;
    for (int s0 = 0; s0 < LTOK; s0 += 32) {
        int s = s0 + lane;
        bool hit = (cb[s] == c) && (mb[s] != 0);
        unsigned m = __ballot_sync(0xffffffffu, hit);
        if (hit) list[base + count + __popc(m & ((1u << lane) - 1u))] = s;
        count += __popc(m);
    }
    if (lane == 0) cnt[g] = count;
}

// ---------------------------------------------------------------------------
// Per-class stats via token lists. Block per (b,c,h).
// ---------------------------------------------------------------------------
__global__ __launch_bounds__(256)
void stats_kernel(const float* __restrict__ K_, const float* __restrict__ V_,
                  const int* __restrict__ list, const int* __restrict__ cnt,
                  float* __restrict__ KV, float* __restrict__ KS)
{
    __shared__ float sk[32][33];
    __shared__ float sv[32][33];
    __shared__ int   st[32];

    int bid = blockIdx.x;
    int h = bid & 7;
    int c = (bid >> 3) & 7;
    int b = bid >> 6;
    int g = b * 8 + c;

    int tid = threadIdx.x;
    int d  = tid >> 3;
    int e0 = (tid & 7) * 4;

    float a0 = 0.f, a1 = 0.f, a2 = 0.f, a3 = 0.f;
    float ssum = 0.f;

    const float* Kb = K_ + (size_t)b * LTOK * CDIM + h * DHEAD;
    const float* Vb = V_ + (size_t)b * LTOK * CDIM + h * DHEAD;
    int n = cnt[g];
    int base = g * LTOK;

    for (int i0 = 0; i0 < n; i0 += 32) {
        if (tid < 32) st[tid] = (i0 + tid < n) ? list[base + i0 + tid] : -1;
        __syncthreads();
        #pragma unroll
        for (int i = 0; i < 4; i++) {
            int idx = tid + i * 256;
            int s = idx >> 5;
            int dd = idx & 31;
            int t = st[s];
            float kk = 0.f, vv = 0.f;
            if (t >= 0) {
                kk = Kb[(size_t)t * CDIM + dd];
                vv = Vb[(size_t)t * CDIM + dd];
            }
            sk[s][dd] = kk;
            sv[s][dd] = vv;
        }
        __syncthreads();
        #pragma unroll
        for (int s = 0; s < 32; s++) {
            float kd = sk[s][d];
            a0 += kd * sv[s][e0 + 0];
            a1 += kd * sv[s][e0 + 1];
            a2 += kd * sv[s][e0 + 2];
            a3 += kd * sv[s][e0 + 3];
        }
        if (tid < 32) {
            #pragma unroll
            for (int s = 0; s < 32; s++) ssum += sk[s][tid];
        }
        __syncthreads();
    }

    size_t o = ((((size_t)b * NPROT + c) * HEADS + h) * DHEAD + d) * DHEAD + e0;
    KV[o + 0] = a0; KV[o + 1] = a1; KV[o + 2] = a2; KV[o + 3] = a3;
    if (tid < 32) KS[(((size_t)b * NPROT + c) * HEADS + h) * DHEAD + tid] = ssum;
}

// ---------------------------------------------------------------------------
// Apply: block per (b,c); kv/ks in SMEM; warp/token; writes msg hi/lo fp16.
// ---------------------------------------------------------------------------
__global__ __launch_bounds__(256)
void apply_kernel(const float* __restrict__ Q, const float* __restrict__ KV,
                  const float* __restrict__ KS, const int* __restrict__ list,
                  const int* __restrict__ cnt,
                  __half* __restrict__ MH, __half* __restrict__ ML)
{
    __shared__ float skv[HEADS][DHEAD][DHEAD];
    __shared__ float sks[HEADS][DHEAD];

    int g = blockIdx.x;              // b*8 + c
    int b = g >> 3;
    int tid = threadIdx.x;
    int w = tid >> 5, lane = tid & 31;

    for (int i = tid; i < HEADS * DHEAD * DHEAD; i += 256)
        skv[i >> 10][(i >> 5) & 31][i & 31] = KV[(size_t)g * HEADS * DHEAD * DHEAD + i];
    for (int i = tid; i < HEADS * DHEAD; i += 256)
        sks[i >> 5][i & 31] = KS[(size_t)g * HEADS * DHEAD + i];
    __syncthreads();

    int n = cnt[g];
    int base = g * LTOK;

    for (int i0 = 0; i0 < n; i0 += 8) {
        int ii = i0 + w;
        if (ii < n) {
            int t = list[base + ii];
            size_t roff = ((size_t)b * LTOK + t) * CDIM;
            const float* qrow = Q + roff;
            #pragma unroll
            for (int h = 0; h < HEADS; h++) {
                float qd = qrow[h * 32 + lane];
                float den = warp_sum(qd * sks[h][lane]) + EPS_ATTN;
                float num = 0.f;
                #pragma unroll
                for (int dd = 0; dd < 32; dd++)
                    num += __shfl_sync(0xffffffffu, qd, dd) * skv[h][dd][lane];
                float m = num / den;
                split_store(m, MH + roff + h * 32 + lane, ML + roff + h * 32 + lane);
            }
        }
    }
}

// ---------------------------------------------------------------------------
// LayerNorm: reads fp32, writes fp16 hi/lo (warp/token)
// ---------------------------------------------------------------------------
__global__ __launch_bounds__(256)
void ln_kernel(const float* __restrict__ X, const float* __restrict__ g,
               const float* __restrict__ b,
               __half* __restrict__ YH, __half* __restrict__ YL)
{
    int tok = blockIdx.x * 8 + (threadIdx.x >> 5);
    int lane = threadIdx.x & 31;
    const float* x = X + (size_t)tok * CDIM;
    float v[8], s = 0.f;
    #pragma unroll
    for (int i = 0; i < 8; i++) { v[i] = x[i * 32 + lane]; s += v[i]; }
    float mean = warp_sum(s) * (1.f / 256.f);
    float s2 = 0.f;
    #pragma unroll
    for (int i = 0; i < 8; i++) { float dd = v[i] - mean; s2 += dd * dd; }
    float rs = rsqrtf(warp_sum(s2) * (1.f / 256.f) + EPS_LN);
    size_t roff = (size_t)tok * CDIM;
    #pragma unroll
    for (int i = 0; i < 8; i++) {
        int cc = i * 32 + lane;
        float y = (v[i] - mean) * rs * g[cc] + b[cc];
        split_store(y, YH + roff + cc, YL + roff + cc);
    }
}

// ---------------------------------------------------------------------------
// Final: x += LN(z)*g2+b2 at valid tokens; refresh x hi/lo.
// ---------------------------------------------------------------------------
__global__ __launch_bounds__(256)
void final_kernel(const float* __restrict__ Z, const float* __restrict__ g,
                  const float* __restrict__ b, const int* __restrict__ mask,
                  float* __restrict__ X,
                  __half* __restrict__ XH, __half* __restrict__ XL)
{
    int tok = blockIdx.x * 8 + (threadIdx.x >> 5);
    int lane = threadIdx.x & 31;
    if (mask[tok] == 0) return;
    const float* z = Z + (size_t)tok * CDIM;
    float v[8], s = 0.f;
    #pragma unroll
    for (int i = 0; i < 8; i++) { v[i] = z[i * 32 + lane]; s += v[i]; }
    float mean = warp_sum(s) * (1.f / 256.f);
    float s2 = 0.f;
    #pragma unroll
    for (int i = 0; i < 8; i++) { float dd = v[i] - mean; s2 += dd * dd; }
    float rs = rsqrtf(warp_sum(s2) * (1.f / 256.f) + EPS_LN);
    size_t roff = (size_t)tok * CDIM;
    float* x = X + roff;
    #pragma unroll
    for (int i = 0; i < 8; i++) {
        int cc = i * 32 + lane;
        float xn = x[cc] + (v[i] - mean) * rs * g[cc] + b[cc];
        x[cc] = xn;
        split_store(xn, XH + roff + cc, XL + roff + cc);
    }
}

// ---------------------------------------------------------------------------
// Copy + split init
// ---------------------------------------------------------------------------
__global__ void copy_split_kernel(const float* __restrict__ s, float* __restrict__ d,
                                  __half* __restrict__ dh,
                                  __half* __restrict__ dl, int n)
{
    int i = blockIdx.x * blockDim.x + threadIdx.x;
    int stride = gridDim.x * blockDim.x;
    for (; i < n; i += stride) {
        float v = s[i];
        d[i] = v;
        split_store(v, dh + i, dl + i);
    }
}
__global__ void copy_kernel(const float* __restrict__ s, float* __restrict__ d, int n)
{
    int i = blockIdx.x * blockDim.x + threadIdx.x;
    int stride = gridDim.x * blockDim.x;
    for (; i < n; i += stride) d[i] = s[i];
}

// ---------------------------------------------------------------------------
// Host orchestration
// ---------------------------------------------------------------------------
struct Bufs {
    float *q, *k, *v, *kv, *ks;
    __half *mh, *ml, *hh, *hl;
};

static void run_layer(float* x, __half* xh, __half* xl,
                      const __half* sh, const __half* sl,
                      const int* listx, const int* cntx,
                      const int* listsrc, const int* cntsrc,
                      const int* maskx,
                      const __half* wh,
                      const float* gg1, const float* bb1,
                      const float* gg2, const float* bb2,
                      const Bufs& B)
{
    dim3 blk(256);
    dim3 gN256(2, NTOK / 128);
    dim3 gN512(4, NTOK / 128);

    gemm_as<1, 0, false><<<gN256, blk, DYN_SMEM>>>(xh, xl, nullptr, nullptr, CDIM,
        wh + WOFF_Q, 256, B.q, nullptr, nullptr, CDIM);
    gemm_as<1, 0, false><<<gN256, blk, DYN_SMEM>>>(sh, sl, nullptr, nullptr, CDIM,
        wh + WOFF_K, 256, B.k, nullptr, nullptr, CDIM);
    gemm_as<0, 0, false><<<gN256, blk, DYN_SMEM>>>(sh, sl, nullptr, nullptr, CDIM,
        wh + WOFF_V, 256, B.v, nullptr, nullptr, CDIM);

    stats_kernel<<<BATCH * NPROT * HEADS, blk>>>(B.k, B.v, listsrc, cntsrc, B.kv, B.ks);
    apply_kernel<<<BATCH * NPROT, blk>>>(B.q, B.kv, B.ks, listx, cntx, B.mh, B.ml);

    gemm_as<0, 0, false><<<gN256, blk, DYN_SMEM>>>(B.mh, B.ml, nullptr, nullptr, CDIM,
        wh + WOFF_M, 256, B.k, nullptr, nullptr, CDIM);   // t
    ln_kernel<<<NTOK / 8, blk>>>(B.k, gg1, bb1, B.mh, B.ml);             // u

    gemm_as<2, 1, true ><<<gN512, blk, DYN_SMEM>>>(xh, xl, B.mh, B.ml, CDIM,
        wh + WOFF_1, 512, nullptr, B.hh, B.hl, 2 * CDIM);
    gemm_as<0, 0, false><<<gN256, blk, DYN_SMEM>>>(B.hh, B.hl, nullptr, nullptr, 2 * CDIM,
        wh + WOFF_2, 512, B.q, nullptr, nullptr, CDIM);   // z
    final_kernel<<<NTOK / 8, blk>>>(B.q, gg2, bb2, maskx, x, xh, xl);
}

extern "C" void kernel_launch(void* const* d_in, const int* in_sizes, int n_in,
                              void* d_out, int out_size)
{
    const float* feat0 = (const float*)d_in[0];
    const float* feat1 = (const float*)d_in[1];
    const int*   mask0 = (const int*)  d_in[2];
    const int*   mask1 = (const int*)  d_in[3];
    const float* f0wp  = (const float*)d_in[4];
    const float* f1wp  = (const float*)d_in[5];
    const float* proto = (const float*)d_in[6];
    const float* Wq    = (const float*)d_in[7];
    const float* Wk    = (const float*)d_in[8];
    const float* Wv    = (const float*)d_in[9];
    const float* Wm    = (const float*)d_in[10];
    const float* W1    = (const float*)d_in[11];
    const float* W2    = (const float*)d_in[12];
    const float* G1    = (const float*)d_in[13];
    const float* B1    = (const float*)d_in[14];
    const float* G2    = (const float*)d_in[15];
    const float* B2    = (const float*)d_in[16];

    cudaFuncSetAttribute(gemm_as<0, 0, false>, cudaFuncAttributeMaxDynamicSharedMemorySize, DYN_SMEM);
    cudaFuncSetAttribute(gemm_as<1, 0, false>, cudaFuncAttributeMaxDynamicSharedMemorySize, DYN_SMEM);
    cudaFuncSetAttribute(gemm_as<2, 1, true >, cudaFuncAttributeMaxDynamicSharedMemorySize, DYN_SMEM);

    float* out = (float*)d_out;
    float* x0     = out + OF_F0;
    float* x1     = out + OF_F1;
    float* cls0f  = out + OF_C0;
    float* cls1f  = out + OF_C1;
    float* f0p    = out + OF_F0P;
    float* f1p    = out + OF_F1P;
    float* protoO = out + OF_PROT;

    Bufs B;
    int *c0, *c1, *l0, *l1, *n0, *n1;
    __half *wh, *x0h, *x0l, *x1h, *x1l;
    cudaGetSymbolAddress((void**)&B.q,  g_q);
    cudaGetSymbolAddress((void**)&B.k,  g_k);
    cudaGetSymbolAddress((void**)&B.v,  g_v);
    cudaGetSymbolAddress((void**)&B.kv, g_kv);
    cudaGetSymbolAddress((void**)&B.ks, g_ks);
    cudaGetSymbolAddress((void**)&B.mh, g_mh);
    cudaGetSymbolAddress((void**)&B.ml, g_ml);
    cudaGetSymbolAddress((void**)&B.hh, g_hh);
    cudaGetSymbolAddress((void**)&B.hl, g_hl);
    cudaGetSymbolAddress((void**)&c0,  g_cls0);
    cudaGetSymbolAddress((void**)&c1,  g_cls1);
    cudaGetSymbolAddress((void**)&l0,  g_list0);
    cudaGetSymbolAddress((void**)&l1,  g_list1);
    cudaGetSymbolAddress((void**)&n0,  g_cnt0);
    cudaGetSymbolAddress((void**)&n1,  g_cnt1);
    cudaGetSymbolAddress((void**)&wh,  g_wh);
    cudaGetSymbolAddress((void**)&x0h, g_x0h);
    cudaGetSymbolAddress((void**)&x0l, g_x0l);
    cudaGetSymbolAddress((void**)&x1h, g_x1h);
    cudaGetSymbolAddress((void**)&x1l, g_x1l);

    // Init: features into output buffer + fp16 hi/lo working copies.
    copy_split_kernel<<<2048, 256>>>(feat0, x0, x0h, x0l, NTOK * CDIM);
    copy_split_kernel<<<2048, 256>>>(feat1, x1, x1h, x1l, NTOK * CDIM);
    copy_kernel<<<8, 256>>>(proto, protoO, NPROT * CDIM);

    classify_kernel<<<NTOK / 8, 256>>>(f0wp, proto, f0p, cls0f, c0);
    classify_kernel<<<NTOK / 8, 256>>>(f1wp, proto, f1p, cls1f, c1);
    build_list<<<BATCH * NPROT, 32>>>(c0, mask0, l0, n0);
    build_list<<<BATCH * NPROT, 32>>>(c1, mask1, l1, n1);

    // Weight prep (transpose + fp16), all layers.
    for (int i = 0; i < NLAYER; i++) {
        __half* hb = wh + (size_t)i * WLSZ;
        prep_w<<<(65536 + 255) / 256, 256>>>(Wq + (size_t)i * 65536, 256, 256, hb + WOFF_Q);
        prep_w<<<(65536 + 255) / 256, 256>>>(Wk + (size_t)i * 65536, 256, 256, hb + WOFF_K);
        prep_w<<<(65536 + 255) / 256, 256>>>(Wv + (size_t)i * 65536, 256, 256, hb + WOFF_V);
        prep_w<<<(65536 + 255) / 256, 256>>>(Wm + (size_t)i * 65536, 256, 256, hb + WOFF_M);
        prep_w<<<(262144 + 255) / 256, 256>>>(W1 + (size_t)i * 262144, 512, 512, hb + WOFF_1);
        prep_w<<<(131072 + 255) / 256, 256>>>(W2 + (size_t)i * 131072, 512, 256, hb + WOFF_2);
    }

    for (int i = 0; i < NLAYER; i++) {
        const __half* hb = wh + (size_t)i * WLSZ;
        const float* gg1 = G1 + (size_t)i * CDIM;
        const float* bb1 = B1 + (size_t)i * CDIM;
        const float* gg2 = G2 + (size_t)i * CDIM;
        const float* bb2 = B2 + (size_t)i * CDIM;

        if ((i & 1) == 0) {  // self-self
            run_layer(x0, x0h, x0l, x0h, x0l, l0, n0, l0, n0, mask0,
                      hb, gg1, bb1, gg2, bb2, B);
            run_layer(x1, x1h, x1l, x1h, x1l, l1, n1, l1, n1, mask1,
                      hb, gg1, bb1, gg2, bb2, B);
        } else {             // cross-self: feat0 attends feat1, then feat1 attends UPDATED feat0
            run_layer(x0, x0h, x0l, x1h, x1l, l0, n0, l1, n1, mask0,
                      hb, gg1, bb1, gg2, bb2, B);
            run_layer(x1, x1h, x1l, x0h, x0l, l1, n1, l0, n0, mask1,
                      hb, gg1, bb1, gg2, bb2, B);
        }
    }
    (void)in_sizes; (void)n_in; (void)out_size;
}

// round 6
// speedup vs baseline: 1.1652x; 1.0144x over previous
#include <cuda_runtime.h>
#include <cuda_fp16.h>
#include <math.h>
#include <stdint.h>

// ---------------------------------------------------------------------------
// Problem constants
// ---------------------------------------------------------------------------
#define BATCH 8
#define LTOK  4800
#define CDIM  256
#define HEADS 8
#define DHEAD 32
#define NPROT 8
#define NLAYER 4
#define NTOK  (BATCH * LTOK)          // 38400
#define EPS_ATTN 1e-6f
#define EPS_LN   1e-5f
#define QKVS  768                      // fused q|k|v row stride

// Output layout (floats), tuple order:
// feat0, feat1, class0, class1, f0p, f1p, prototype
#define OF_F0    0
#define OF_F1    (NTOK * CDIM)
#define OF_C0    (2 * NTOK * CDIM)
#define OF_C1    (OF_C0 + NTOK)
#define OF_F0P   (OF_C1 + NTOK)
#define OF_F1P   (OF_F0P + NTOK * NPROT)
#define OF_PROT  (OF_F1P + NTOK * NPROT)

// ---------------------------------------------------------------------------
// Device scratch (no allocation allowed)
// ---------------------------------------------------------------------------
__device__ __align__(16) float g_qkv[NTOK * QKVS];   // q | k(phi) | v
__device__ __align__(16) float g_t  [NTOK * CDIM];   // t (msg@Wm), then z
__device__ __align__(16) float g_kv [BATCH * NPROT * HEADS * DHEAD * DHEAD];
__device__ __align__(16) float g_ks [BATCH * NPROT * HEADS * DHEAD];
__device__ int   g_cls0[NTOK];
__device__ int   g_cls1[NTOK];
__device__ int   g_list0[BATCH * NPROT * LTOK];
__device__ int   g_list1[BATCH * NPROT * LTOK];
__device__ int   g_cnt0[BATCH * NPROT];
__device__ int   g_cnt1[BATCH * NPROT];

// fp16 hi/lo activation buffers
__device__ __align__(16) __half g_x0h[NTOK * CDIM];
__device__ __align__(16) __half g_x0l[NTOK * CDIM];
__device__ __align__(16) __half g_x1h[NTOK * CDIM];
__device__ __align__(16) __half g_x1l[NTOK * CDIM];
__device__ __align__(16) __half g_mh [NTOK * CDIM];   // msg, then LN(u)
__device__ __align__(16) __half g_ml [NTOK * CDIM];
__device__ __align__(16) __half g_hh [NTOK * 2 * CDIM];
__device__ __align__(16) __half g_hl [NTOK * 2 * CDIM];

// Transposed fp16 weights per layer: [Wq|Wk|Wv] (768x256), Wm (256x256),
// W1 (512x512), W2 (256x512); all stored [N,K] K-contiguous.
#define WOFF_QKV 0
#define WOFF_M   196608
#define WOFF_1   262144
#define WOFF_2   524288
#define WLSZ     655360
__device__ __align__(16) __half g_wh[NLAYER * WLSZ];

// ---------------------------------------------------------------------------
// Helpers
// ---------------------------------------------------------------------------
__device__ __forceinline__ uint32_t smem_u32(const void* p) {
    uint32_t a;
    asm("{ .reg .u64 t; cvta.to.shared.u64 t, %1; cvt.u32.u64 %0, t; }"
        : "=r"(a) : "l"(p));
    return a;
}
__device__ __forceinline__ float warp_sum(float v) {
    #pragma unroll
    for (int o = 16; o; o >>= 1) v += __shfl_xor_sync(0xffffffffu, v, o);
    return v;
}
__device__ __forceinline__ void ldsm4(uint32_t* r, uint32_t addr) {
    asm volatile("ldmatrix.sync.aligned.m8n8.x4.shared.b16 {%0,%1,%2,%3}, [%4];"
                 : "=r"(r[0]), "=r"(r[1]), "=r"(r[2]), "=r"(r[3]) : "r"(addr));
}
__device__ __forceinline__ void mma16816(float* c, const uint32_t* a,
                                         uint32_t b0, uint32_t b1) {
    asm volatile(
        "mma.sync.aligned.m16n8k16.row.col.f32.f16.f16.f32 "
        "{%0,%1,%2,%3}, {%4,%5,%6,%7}, {%8,%9}, {%0,%1,%2,%3};"
        : "+f"(c[0]), "+f"(c[1]), "+f"(c[2]), "+f"(c[3])
        : "r"(a[0]), "r"(a[1]), "r"(a[2]), "r"(a[3]), "r"(b0), "r"(b1));
}
__device__ __forceinline__ void cpasync16(uint32_t dst, const __half* src) {
    asm volatile("cp.async.cg.shared.global [%0], [%1], 16;"
                 :: "r"(dst), "l"(__cvta_generic_to_global(src)));
}
#define CP_COMMIT() asm volatile("cp.async.commit_group;" ::: "memory")

__device__ __forceinline__ void split_store(float v, __half* ph, __half* pl) {
    __half h = __float2half(v);
    *ph = h;
    *pl = __float2half(v - __half2float(h));
}
__device__ __forceinline__ float phi_f(float v) {
    return (v > 0.f) ? (v + 1.f) : expf(v);   // elu(v)+1
}

// ---------------------------------------------------------------------------
// mma.sync GEMM: C[:, coloff + n] = f(A[M,K] @ W[K,N]), fp16 hi/lo 2-pass
// (A = Ahi + Alo exactly; W rounded to fp16).
// A pre-split fp16 hi/lo [M,K]; B fp16 [N,K] K-contiguous.
// CTA tile 128x128, K-chunks of 32, 3-stage cp.async pipeline.
// MMA schedule: all 16 hi-pass MMAs, then all 16 lo-pass (RAW distance 16).
// EPI: 0 none, 2 relu, 3 phi for local col < thresh else identity.
// OUT: 0 fp32, 1 fp16 hi/lo split. CONCAT: A k<256, A2 k>=256.
// ---------------------------------------------------------------------------
#define RS      40                     // SMEM row stride (fp16) -> 80B
#define SA_HI   0
#define SA_LO   10240
#define SB_HI   20480
#define STG_SZ  30720
#define NSTAGE  3
#define DYN_SMEM (NSTAGE * STG_SZ)     // 92160

template <int EPI, int OUT, bool CONCAT>
__global__ __launch_bounds__(256, 2)
void gemm_as(const __half* __restrict__ Ahi, const __half* __restrict__ Alo,
             const __half* __restrict__ A2hi, const __half* __restrict__ A2lo,
             int lda,
             const __half* __restrict__ Bh,
             int K,
             float* __restrict__ Cf, __half* __restrict__ Chi,
             __half* __restrict__ Clo, int cstride, int coloff, int thresh)
{
    extern __shared__ __align__(128) char sm[];
    const uint32_t sbase = smem_u32(sm);
    const int tid  = threadIdx.x;
    const int lane = tid & 31;
    const int wid  = tid >> 5;
    const int wm   = wid >> 1;         // 0..3 -> M offset wm*32
    const int wn   = wid & 1;          // 0..1 -> N offset wn*64
    const int m0   = blockIdx.y * 128;
    const int n0   = blockIdx.x * 128;
    const int chunks = K >> 5;

    float acc[2][8][4];
    #pragma unroll
    for (int i = 0; i < 2; i++)
        #pragma unroll
        for (int j = 0; j < 8; j++)
            #pragma unroll
            for (int t = 0; t < 4; t++) acc[i][j][t] = 0.f;

    const int car = tid >> 2;          // 0..63 (x2 -> 128 rows)
    const int cas = tid & 3;           // seg*8 fp16 = 16B

    auto issue = [&](int c) {
        const uint32_t stg = sbase + (c % NSTAGE) * STG_SZ;
        const int k0 = c * 32;
        const __half* ah = Ahi;
        const __half* al = Alo;
        int koff = k0;
        if (CONCAT && k0 >= 256) { ah = A2hi; al = A2lo; koff = k0 - 256; }
        #pragma unroll
        for (int i = 0; i < 2; i++) {
            int row = car + i * 64;
            uint32_t doff = (uint32_t)(row * RS + cas * 8) * 2;
            size_t agoff = (size_t)(m0 + row) * lda + koff + cas * 8;
            cpasync16(stg + SA_HI + doff, ah + agoff);
            cpasync16(stg + SA_LO + doff, al + agoff);
            size_t bgoff = (size_t)(n0 + row) * K + k0 + cas * 8;
            cpasync16(stg + SB_HI + doff, Bh + bgoff);
        }
    };

    issue(0); CP_COMMIT();
    if (chunks > 1) { issue(1); CP_COMMIT(); }

    const int arow = wm * 32 + (lane & 15);
    const int ako  = (lane >> 4) << 3;
    const int brow = wn * 64 + ((lane >> 4) << 3) + (lane & 7);
    const int bko  = ((lane >> 3) & 1) << 3;

    for (int c = 0; c < chunks; c++) {
        if (c + 2 < chunks) {
            issue(c + 2); CP_COMMIT();
            asm volatile("cp.async.wait_group 2;" ::: "memory");
        } else if (c + 1 < chunks) {
            asm volatile("cp.async.wait_group 1;" ::: "memory");
        } else {
            asm volatile("cp.async.wait_group 0;" ::: "memory");
        }
        __syncthreads();

        const uint32_t stg = sbase + (c % NSTAGE) * STG_SZ;

        #pragma unroll
        for (int ks = 0; ks < 2; ks++) {
            const int ko = ks * 16;
            uint32_t ah[2][4], al[2][4], bf[4][4];
            #pragma unroll
            for (int mt = 0; mt < 2; mt++) {
                uint32_t ad = stg + SA_HI + (uint32_t)((arow + mt * 16) * RS + ko + ako) * 2;
                ldsm4(ah[mt], ad);
                ldsm4(al[mt], ad + (SA_LO - SA_HI));
            }
            #pragma unroll
            for (int g = 0; g < 4; g++) {
                uint32_t bd = stg + SB_HI + (uint32_t)((brow + g * 16) * RS + ko + bko) * 2;
                ldsm4(bf[g], bd);
            }
            // hi pass: 16 independent MMAs
            #pragma unroll
            for (int mt = 0; mt < 2; mt++)
                #pragma unroll
                for (int g = 0; g < 4; g++) {
                    mma16816(acc[mt][g * 2 + 0], ah[mt], bf[g][0], bf[g][1]);
                    mma16816(acc[mt][g * 2 + 1], ah[mt], bf[g][2], bf[g][3]);
                }
            // lo pass: RAW on acc now 16 issues away
            #pragma unroll
            for (int mt = 0; mt < 2; mt++)
                #pragma unroll
                for (int g = 0; g < 4; g++) {
                    mma16816(acc[mt][g * 2 + 0], al[mt], bf[g][0], bf[g][1]);
                    mma16816(acc[mt][g * 2 + 1], al[mt], bf[g][2], bf[g][3]);
                }
        }
        __syncthreads();
    }

    // Epilogue
    const int gp = lane >> 2;
    const int tq = lane & 3;
    #pragma unroll
    for (int mt = 0; mt < 2; mt++) {
        #pragma unroll
        for (int nt = 0; nt < 8; nt++) {
            float* cc = acc[mt][nt];
            int lcol = n0 + wn * 64 + nt * 8 + tq * 2;      // local col (pair base)
            bool dophi = (EPI == 3) && (lcol < thresh);
            #pragma unroll
            for (int t = 0; t < 4; t++) {
                float v = cc[t];
                if (EPI == 2) v = fmaxf(v, 0.f);
                else if (EPI == 3 && dophi) v = phi_f(v);
                cc[t] = v;
            }
            size_t row = (size_t)(m0 + wm * 32 + mt * 16 + gp);
            int col = coloff + lcol;
            if (OUT == 0) {
                *(float2*)(Cf + row * cstride + col)       = make_float2(cc[0], cc[1]);
                *(float2*)(Cf + (row + 8) * cstride + col) = make_float2(cc[2], cc[3]);
            } else {
                #pragma unroll
                for (int rr = 0; rr < 2; rr++) {
                    size_t o = (row + rr * 8) * cstride + col;
                    float v0 = cc[rr * 2 + 0], v1 = cc[rr * 2 + 1];
                    __half h0 = __float2half(v0);
                    __half h1 = __float2half(v1);
                    __half2 hh = __halves2half2(h0, h1);
                    __half2 ll = __halves2half2(
                        __float2half(v0 - __half2float(h0)),
                        __float2half(v1 - __half2float(h1)));
                    *(uint32_t*)(Chi + o) = *(uint32_t*)&hh;
                    *(uint32_t*)(Clo + o) = *(uint32_t*)&ll;
                }
            }
        }
    }
}

// ---------------------------------------------------------------------------
// Weight prep: out[n*K + k] = fp16(W[k*N + n])
// ---------------------------------------------------------------------------
__global__ void prep_w(const float* __restrict__ W, int Kd, int Nd,
                       __half* __restrict__ hi)
{
    int idx = blockIdx.x * blockDim.x + threadIdx.x;
    if (idx >= Kd * Nd) return;
    int n = idx / Kd;
    int k = idx - n * Kd;
    hi[idx] = __float2half(W[(size_t)k * Nd + n]);
}

// ---------------------------------------------------------------------------
// Classification (warp/token)
// ---------------------------------------------------------------------------
__global__ __launch_bounds__(256)
void classify_kernel(const float* __restrict__ fwp, const float* __restrict__ proto,
                     float* __restrict__ out_fp, float* __restrict__ out_clsf,
                     int* __restrict__ cls)
{
    __shared__ float sp[NPROT][CDIM];
    int tid = threadIdx.x;
    #pragma unroll
    for (int i = 0; i < 8; i++) {
        int idx = tid + i * 256;
        sp[idx >> 8][idx & 255] = proto[idx];
    }
    __syncthreads();

    int tok = blockIdx.x * 8 + (tid >> 5);
    int lane = tid & 31;
    const float* f = fwp + (size_t)tok * CDIM;

    float acc[NPROT];
    #pragma unroll
    for (int p = 0; p < NPROT; p++) acc[p] = 0.f;
    #pragma unroll
    for (int i = 0; i < 8; i++) {
        float x = f[lane + i * 32];
        #pragma unroll
        for (int p = 0; p < NPROT; p++) acc[p] += x * sp[p][lane + i * 32];
    }
    #pragma unroll
    for (int p = 0; p < NPROT; p++) acc[p] = warp_sum(acc[p]);

    if (lane < NPROT) out_fp[(size_t)tok * NPROT + lane] = acc[lane];
    if (lane == 0) {
        int best = 0; float bv = acc[0];
        #pragma unroll
        for (int p = 1; p < NPROT; p++) if (acc[p] > bv) { bv = acc[p]; best = p; }
        cls[tok] = best;
        out_clsf[tok] = (float)best;
    }
}

// ---------------------------------------------------------------------------
// Token list build (ballot compaction), 32 thr/block
// ---------------------------------------------------------------------------
__global__ void build_list(const int* __restrict__ cls, const int* __restrict__ mask,
                           int* __restrict__ list, int* __restrict__ cnt)
{
    int g = blockIdx.x;              // b*8 + c
    int b = g >> 3, c = g & 7;
    int lane = threadIdx.x;
    const int* cb = cls + b * LTOK;
    const int* mb = mask + b * LTOK;
    int base = g * LTOK;
    int count = 0;
    for (int s0 = 0; s0 < LTOK; s0 += 32) {
        int s = s0 + lane;
        bool hit = (cb[s] == c) && (mb[s] != 0);
        unsigned m = __ballot_sync(0xffffffffu, hit);
        if (hit) list[base + count + __popc(m & ((1u << lane) - 1u))] = s;
        count += __popc(m);
    }
    if (lane == 0) cnt[g] = count;
}

// ---------------------------------------------------------------------------
// Per-class stats via token lists; reads k/v from fused qkv (stride 768).
// Block per (b,c,h).
// ---------------------------------------------------------------------------
__global__ __launch_bounds__(256)
void stats_kernel(const float* __restrict__ QKV,
                  const int* __restrict__ list, const int* __restrict__ cnt,
                  float* __restrict__ KV, float* __restrict__ KS)
{
    __shared__ float sk[32][33];
    __shared__ float sv[32][33];
    __shared__ int   st[32];

    int bid = blockIdx.x;
    int h = bid & 7;
    int c = (bid >> 3) & 7;
    int b = bid >> 6;
    int g = b * 8 + c;

    int tid = threadIdx.x;
    int d  = tid >> 3;
    int e0 = (tid & 7) * 4;

    float a0 = 0.f, a1 = 0.f, a2 = 0.f, a3 = 0.f;
    float ssum = 0.f;

    const float* Kb = QKV + (size_t)b * LTOK * QKVS + 256 + h * DHEAD;
    const float* Vb = QKV + (size_t)b * LTOK * QKVS + 512 + h * DHEAD;
    int n = cnt[g];
    int base = g * LTOK;

    for (int i0 = 0; i0 < n; i0 += 32) {
        if (tid < 32) st[tid] = (i0 + tid < n) ? list[base + i0 + tid] : -1;
        __syncthreads();
        #pragma unroll
        for (int i = 0; i < 4; i++) {
            int idx = tid + i * 256;
            int s = idx >> 5;
            int dd = idx & 31;
            int t = st[s];
            float kk = 0.f, vv = 0.f;
            if (t >= 0) {
                kk = Kb[(size_t)t * QKVS + dd];
                vv = Vb[(size_t)t * QKVS + dd];
            }
            sk[s][dd] = kk;
            sv[s][dd] = vv;
        }
        __syncthreads();
        #pragma unroll
        for (int s = 0; s < 32; s++) {
            float kd = sk[s][d];
            a0 += kd * sv[s][e0 + 0];
            a1 += kd * sv[s][e0 + 1];
            a2 += kd * sv[s][e0 + 2];
            a3 += kd * sv[s][e0 + 3];
        }
        if (tid < 32) {
            #pragma unroll
            for (int s = 0; s < 32; s++) ssum += sk[s][tid];
        }
        __syncthreads();
    }

    size_t o = ((((size_t)b * NPROT + c) * HEADS + h) * DHEAD + d) * DHEAD + e0;
    KV[o + 0] = a0; KV[o + 1] = a1; KV[o + 2] = a2; KV[o + 3] = a3;
    if (tid < 32) KS[(((size_t)b * NPROT + c) * HEADS + h) * DHEAD + tid] = ssum;
}

// ---------------------------------------------------------------------------
// Apply: block per (b,c); kv/ks in SMEM; warp/token; q from fused qkv;
// writes msg hi/lo fp16.
// ---------------------------------------------------------------------------
__global__ __launch_bounds__(256)
void apply_kernel(const float* __restrict__ QKV, const float* __restrict__ KV,
                  const float* __restrict__ KS, const int* __restrict__ list,
                  const int* __restrict__ cnt,
                  __half* __restrict__ MH, __half* __restrict__ ML)
{
    __shared__ float skv[HEADS][DHEAD][DHEAD];
    __shared__ float sks[HEADS][DHEAD];

    int g = blockIdx.x;              // b*8 + c
    int b = g >> 3;
    int tid = threadIdx.x;
    int w = tid >> 5, lane = tid & 31;

    for (int i = tid; i < HEADS * DHEAD * DHEAD; i += 256)
        skv[i >> 10][(i >> 5) & 31][i & 31] = KV[(size_t)g * HEADS * DHEAD * DHEAD + i];
    for (int i = tid; i < HEADS * DHEAD; i += 256)
        sks[i >> 5][i & 31] = KS[(size_t)g * HEADS * DHEAD + i];
    __syncthreads();

    int n = cnt[g];
    int base = g * LTOK;

    for (int i0 = 0; i0 < n; i0 += 8) {
        int ii = i0 + w;
        if (ii < n) {
            int t = list[base + ii];
            const float* qrow = QKV + ((size_t)b * LTOK + t) * QKVS;
            size_t moff = ((size_t)b * LTOK + t) * CDIM;
            #pragma unroll
            for (int h = 0; h < HEADS; h++) {
                float qd = qrow[h * 32 + lane];
                float den = warp_sum(qd * sks[h][lane]) + EPS_ATTN;
                float num = 0.f;
                #pragma unroll
                for (int dd = 0; dd < 32; dd++)
                    num += __shfl_sync(0xffffffffu, qd, dd) * skv[h][dd][lane];
                float m = num / den;
                split_store(m, MH + moff + h * 32 + lane, ML + moff + h * 32 + lane);
            }
        }
    }
}

// ---------------------------------------------------------------------------
// LayerNorm: reads fp32, writes fp16 hi/lo (warp/token)
// ---------------------------------------------------------------------------
__global__ __launch_bounds__(256)
void ln_kernel(const float* __restrict__ X, const float* __restrict__ g,
               const float* __restrict__ b,
               __half* __restrict__ YH, __half* __restrict__ YL)
{
    int tok = blockIdx.x * 8 + (threadIdx.x >> 5);
    int lane = threadIdx.x & 31;
    const float* x = X + (size_t)tok * CDIM;
    float v[8], s = 0.f;
    #pragma unroll
    for (int i = 0; i < 8; i++) { v[i] = x[i * 32 + lane]; s += v[i]; }
    float mean = warp_sum(s) * (1.f / 256.f);
    float s2 = 0.f;
    #pragma unroll
    for (int i = 0; i < 8; i++) { float dd = v[i] - mean; s2 += dd * dd; }
    float rs = rsqrtf(warp_sum(s2) * (1.f / 256.f) + EPS_LN);
    size_t roff = (size_t)tok * CDIM;
    #pragma unroll
    for (int i = 0; i < 8; i++) {
        int cc = i * 32 + lane;
        float y = (v[i] - mean) * rs * g[cc] + b[cc];
        split_store(y, YH + roff + cc, YL + roff + cc);
    }
}

// ---------------------------------------------------------------------------
// Final: x += LN(z)*g2+b2 at valid tokens; refresh x hi/lo.
// ---------------------------------------------------------------------------
__global__ __launch_bounds__(256)
void final_kernel(const float* __restrict__ Z, const float* __restrict__ g,
                  const float* __restrict__ b, const int* __restrict__ mask,
                  float* __restrict__ X,
                  __half* __restrict__ XH, __half* __restrict__ XL)
{
    int tok = blockIdx.x * 8 + (threadIdx.x >> 5);
    int lane = threadIdx.x & 31;
    if (mask[tok] == 0) return;
    const float* z = Z + (size_t)tok * CDIM;
    float v[8], s = 0.f;
    #pragma unroll
    for (int i = 0; i < 8; i++) { v[i] = z[i * 32 + lane]; s += v[i]; }
    float mean = warp_sum(s) * (1.f / 256.f);
    float s2 = 0.f;
    #pragma unroll
    for (int i = 0; i < 8; i++) { float dd = v[i] - mean; s2 += dd * dd; }
    float rs = rsqrtf(warp_sum(s2) * (1.f / 256.f) + EPS_LN);
    size_t roff = (size_t)tok * CDIM;
    float* x = X + roff;
    #pragma unroll
    for (int i = 0; i < 8; i++) {
        int cc = i * 32 + lane;
        float xn = x[cc] + (v[i] - mean) * rs * g[cc] + b[cc];
        x[cc] = xn;
        split_store(xn, XH + roff + cc, XL + roff + cc);
    }
}

// ---------------------------------------------------------------------------
// Copy + split init
// ---------------------------------------------------------------------------
__global__ void copy_split_kernel(const float* __restrict__ s, float* __restrict__ d,
                                  __half* __restrict__ dh,
                                  __half* __restrict__ dl, int n)
{
    int i = blockIdx.x * blockDim.x + threadIdx.x;
    int stride = gridDim.x * blockDim.x;
    for (; i < n; i += stride) {
        float v = s[i];
        d[i] = v;
        split_store(v, dh + i, dl + i);
    }
}
__global__ void copy_kernel(const float* __restrict__ s, float* __restrict__ d, int n)
{
    int i = blockIdx.x * blockDim.x + threadIdx.x;
    int stride = gridDim.x * blockDim.x;
    for (; i < n; i += stride) d[i] = s[i];
}

// ---------------------------------------------------------------------------
// Host orchestration
// ---------------------------------------------------------------------------
struct Bufs {
    float *qkv, *t, *kv, *ks;
    __half *mh, *ml, *hh, *hl;
};

static void run_layer(bool selfself,
                      float* x, __half* xh, __half* xl,
                      const __half* sh, const __half* sl,
                      const int* listx, const int* cntx,
                      const int* listsrc, const int* cntsrc,
                      const int* maskx,
                      const __half* wh,
                      const float* gg1, const float* bb1,
                      const float* gg2, const float* bb2,
                      const Bufs& B)
{
    dim3 blk(256);
    const int MT = NTOK / 128;          // 300

    if (selfself) {
        // fused q|k|v: N=768, phi on cols < 512
        gemm_as<3, 0, false><<<dim3(6, MT), blk, DYN_SMEM>>>(xh, xl, nullptr, nullptr,
            CDIM, wh + WOFF_QKV, 256, B.qkv, nullptr, nullptr, QKVS, 0, 512);
    } else {
        // q: N=256 all phi
        gemm_as<3, 0, false><<<dim3(2, MT), blk, DYN_SMEM>>>(xh, xl, nullptr, nullptr,
            CDIM, wh + WOFF_QKV, 256, B.qkv, nullptr, nullptr, QKVS, 0, 256);
        // k|v from src: N=512, phi on local cols < 256, output cols 256..767
        gemm_as<3, 0, false><<<dim3(4, MT), blk, DYN_SMEM>>>(sh, sl, nullptr, nullptr,
            CDIM, wh + WOFF_QKV + 256 * 256, 256, B.qkv, nullptr, nullptr, QKVS, 256, 256);
    }

    stats_kernel<<<BATCH * NPROT * HEADS, blk>>>(B.qkv, listsrc, cntsrc, B.kv, B.ks);
    apply_kernel<<<BATCH * NPROT, blk>>>(B.qkv, B.kv, B.ks, listx, cntx, B.mh, B.ml);

    gemm_as<0, 0, false><<<dim3(2, MT), blk, DYN_SMEM>>>(B.mh, B.ml, nullptr, nullptr,
        CDIM, wh + WOFF_M, 256, B.t, nullptr, nullptr, CDIM, 0, 0);
    ln_kernel<<<NTOK / 8, blk>>>(B.t, gg1, bb1, B.mh, B.ml);

    gemm_as<2, 1, true ><<<dim3(4, MT), blk, DYN_SMEM>>>(xh, xl, B.mh, B.ml,
        CDIM, wh + WOFF_1, 512, nullptr, B.hh, B.hl, 2 * CDIM, 0, 0);
    gemm_as<0, 0, false><<<dim3(2, MT), blk, DYN_SMEM>>>(B.hh, B.hl, nullptr, nullptr,
        2 * CDIM, wh + WOFF_2, 512, B.t, nullptr, nullptr, CDIM, 0, 0);
    final_kernel<<<NTOK / 8, blk>>>(B.t, gg2, bb2, maskx, x, xh, xl);
}

extern "C" void kernel_launch(void* const* d_in, const int* in_sizes, int n_in,
                              void* d_out, int out_size)
{
    const float* feat0 = (const float*)d_in[0];
    const float* feat1 = (const float*)d_in[1];
    const int*   mask0 = (const int*)  d_in[2];
    const int*   mask1 = (const int*)  d_in[3];
    const float* f0wp  = (const float*)d_in[4];
    const float* f1wp  = (const float*)d_in[5];
    const float* proto = (const float*)d_in[6];
    const float* Wq    = (const float*)d_in[7];
    const float* Wk    = (const float*)d_in[8];
    const float* Wv    = (const float*)d_in[9];
    const float* Wm    = (const float*)d_in[10];
    const float* W1    = (const float*)d_in[11];
    const float* W2    = (const float*)d_in[12];
    const float* G1    = (const float*)d_in[13];
    const float* B1    = (const float*)d_in[14];
    const float* G2    = (const float*)d_in[15];
    const float* B2    = (const float*)d_in[16];

    cudaFuncSetAttribute(gemm_as<0, 0, false>, cudaFuncAttributeMaxDynamicSharedMemorySize, DYN_SMEM);
    cudaFuncSetAttribute(gemm_as<3, 0, false>, cudaFuncAttributeMaxDynamicSharedMemorySize, DYN_SMEM);
    cudaFuncSetAttribute(gemm_as<2, 1, true >, cudaFuncAttributeMaxDynamicSharedMemorySize, DYN_SMEM);

    float* out = (float*)d_out;
    float* x0     = out + OF_F0;
    float* x1     = out + OF_F1;
    float* cls0f  = out + OF_C0;
    float* cls1f  = out + OF_C1;
    float* f0p    = out + OF_F0P;
    float* f1p    = out + OF_F1P;
    float* protoO = out + OF_PROT;

    Bufs B;
    int *c0, *c1, *l0, *l1, *n0, *n1;
    __half *wh, *x0h, *x0l, *x1h, *x1l;
    cudaGetSymbolAddress((void**)&B.qkv, g_qkv);
    cudaGetSymbolAddress((void**)&B.t,   g_t);
    cudaGetSymbolAddress((void**)&B.kv,  g_kv);
    cudaGetSymbolAddress((void**)&B.ks,  g_ks);
    cudaGetSymbolAddress((void**)&B.mh,  g_mh);
    cudaGetSymbolAddress((void**)&B.ml,  g_ml);
    cudaGetSymbolAddress((void**)&B.hh,  g_hh);
    cudaGetSymbolAddress((void**)&B.hl,  g_hl);
    cudaGetSymbolAddress((void**)&c0,  g_cls0);
    cudaGetSymbolAddress((void**)&c1,  g_cls1);
    cudaGetSymbolAddress((void**)&l0,  g_list0);
    cudaGetSymbolAddress((void**)&l1,  g_list1);
    cudaGetSymbolAddress((void**)&n0,  g_cnt0);
    cudaGetSymbolAddress((void**)&n1,  g_cnt1);
    cudaGetSymbolAddress((void**)&wh,  g_wh);
    cudaGetSymbolAddress((void**)&x0h, g_x0h);
    cudaGetSymbolAddress((void**)&x0l, g_x0l);
    cudaGetSymbolAddress((void**)&x1h, g_x1h);
    cudaGetSymbolAddress((void**)&x1l, g_x1l);

    // Init: features into output buffer + fp16 hi/lo working copies.
    copy_split_kernel<<<2048, 256>>>(feat0, x0, x0h, x0l, NTOK * CDIM);
    copy_split_kernel<<<2048, 256>>>(feat1, x1, x1h, x1l, NTOK * CDIM);
    copy_kernel<<<8, 256>>>(proto, protoO, NPROT * CDIM);

    classify_kernel<<<NTOK / 8, 256>>>(f0wp, proto, f0p, cls0f, c0);
    classify_kernel<<<NTOK / 8, 256>>>(f1wp, proto, f1p, cls1f, c1);
    build_list<<<BATCH * NPROT, 32>>>(c0, mask0, l0, n0);
    build_list<<<BATCH * NPROT, 32>>>(c1, mask1, l1, n1);

    // Weight prep (transpose + fp16): q|k|v packed as rows 0..767.
    for (int i = 0; i < NLAYER; i++) {
        __half* hb = wh + (size_t)i * WLSZ;
        prep_w<<<(65536 + 255) / 256, 256>>>(Wq + (size_t)i * 65536, 256, 256, hb + WOFF_QKV);
        prep_w<<<(65536 + 255) / 256, 256>>>(Wk + (size_t)i * 65536, 256, 256, hb + WOFF_QKV + 256 * 256);
        prep_w<<<(65536 + 255) / 256, 256>>>(Wv + (size_t)i * 65536, 256, 256, hb + WOFF_QKV + 512 * 256);
        prep_w<<<(65536 + 255) / 256, 256>>>(Wm + (size_t)i * 65536, 256, 256, hb + WOFF_M);
        prep_w<<<(262144 + 255) / 256, 256>>>(W1 + (size_t)i * 262144, 512, 512, hb + WOFF_1);
        prep_w<<<(131072 + 255) / 256, 256>>>(W2 + (size_t)i * 131072, 512, 256, hb + WOFF_2);
    }

    for (int i = 0; i < NLAYER; i++) {
        const __half* hb = wh + (size_t)i * WLSZ;
        const float* gg1 = G1 + (size_t)i * CDIM;
        const float* bb1 = B1 + (size_t)i * CDIM;
        const float* gg2 = G2 + (size_t)i * CDIM;
        const float* bb2 = B2 + (size_t)i * CDIM;

        if ((i & 1) == 0) {  // self-self
            run_layer(true, x0, x0h, x0l, x0h, x0l, l0, n0, l0, n0, mask0,
                      hb, gg1, bb1, gg2, bb2, B);
            run_layer(true, x1, x1h, x1l, x1h, x1l, l1, n1, l1, n1, mask1,
                      hb, gg1, bb1, gg2, bb2, B);
        } else {             // cross-self: feat0 attends feat1, then feat1 attends UPDATED feat0
            run_layer(false, x0, x0h, x0l, x1h, x1l, l0, n0, l1, n1, mask0,
                      hb, gg1, bb1, gg2, bb2, B);
            run_layer(false, x1, x1h, x1l, x0h, x0l, l1, n1, l0, n0, mask1,
                      hb, gg1, bb1, gg2, bb2, B);
        }
    }
    (void)in_sizes; (void)n_in; (void)out_size;
}

// round 8
// speedup vs baseline: 1.6627x; 1.4270x over previous
#include <cuda_runtime.h>
#include <cuda_fp16.h>
#include <math.h>
#include <stdint.h>

// ---------------------------------------------------------------------------
// Problem constants
// ---------------------------------------------------------------------------
#define BATCH 8
#define LTOK  4800
#define CDIM  256
#define HEADS 8
#define DHEAD 32
#define NPROT 8
#define NLAYER 4
#define NTOK  (BATCH * LTOK)          // 38400
#define EPS_ATTN 1e-6f
#define EPS_LN   1e-5f
#define QKVS  768                      // fused q|k|v row stride

// Output layout (floats), tuple order:
// feat0, feat1, class0, class1, f0p, f1p, prototype
#define OF_F0    0
#define OF_F1    (NTOK * CDIM)
#define OF_C0    (2 * NTOK * CDIM)
#define OF_C1    (OF_C0 + NTOK)
#define OF_F0P   (OF_C1 + NTOK)
#define OF_F1P   (OF_F0P + NTOK * NPROT)
#define OF_PROT  (OF_F1P + NTOK * NPROT)

// ---------------------------------------------------------------------------
// Device scratch (two sets: stream A / stream B)
// ---------------------------------------------------------------------------
__device__ __align__(16) float g_qkvA[NTOK * QKVS];
__device__ __align__(16) float g_qkvB[NTOK * QKVS];
__device__ __align__(16) float g_tA  [NTOK * CDIM];
__device__ __align__(16) float g_tB  [NTOK * CDIM];
__device__ __align__(16) float g_kvA [BATCH * NPROT * HEADS * DHEAD * DHEAD];
__device__ __align__(16) float g_kvB [BATCH * NPROT * HEADS * DHEAD * DHEAD];
__device__ __align__(16) float g_ksA [BATCH * NPROT * HEADS * DHEAD];
__device__ __align__(16) float g_ksB [BATCH * NPROT * HEADS * DHEAD];
__device__ __align__(16) __half g_mhA[NTOK * CDIM];
__device__ __align__(16) __half g_mlA[NTOK * CDIM];
__device__ __align__(16) __half g_mhB[NTOK * CDIM];
__device__ __align__(16) __half g_mlB[NTOK * CDIM];
__device__ __align__(16) __half g_hhA[NTOK * 2 * CDIM];
__device__ __align__(16) __half g_hlA[NTOK * 2 * CDIM];
__device__ __align__(16) __half g_hhB[NTOK * 2 * CDIM];
__device__ __align__(16) __half g_hlB[NTOK * 2 * CDIM];

__device__ int   g_cls0[NTOK];
__device__ int   g_cls1[NTOK];
__device__ int   g_list0[BATCH * NPROT * LTOK];
__device__ int   g_list1[BATCH * NPROT * LTOK];
__device__ int   g_cnt0[BATCH * NPROT];
__device__ int   g_cnt1[BATCH * NPROT];

// fp16 hi/lo feature buffers
__device__ __align__(16) __half g_x0h[NTOK * CDIM];
__device__ __align__(16) __half g_x0l[NTOK * CDIM];
__device__ __align__(16) __half g_x1h[NTOK * CDIM];
__device__ __align__(16) __half g_x1l[NTOK * CDIM];

// Transposed fp16 weights per layer: [Wq|Wk|Wv] (768x256), Wm, W1, W2 ([N,K])
#define WOFF_QKV 0
#define WOFF_M   196608
#define WOFF_1   262144
#define WOFF_2   524288
#define WLSZ     655360
__device__ __align__(16) __half g_wh[NLAYER * WLSZ];

// ---------------------------------------------------------------------------
// Helpers
// ---------------------------------------------------------------------------
__device__ __forceinline__ uint32_t smem_u32(const void* p) {
    uint32_t a;
    asm("{ .reg .u64 t; cvta.to.shared.u64 t, %1; cvt.u32.u64 %0, t; }"
        : "=r"(a) : "l"(p));
    return a;
}
__device__ __forceinline__ float warp_sum(float v) {
    #pragma unroll
    for (int o = 16; o; o >>= 1) v += __shfl_xor_sync(0xffffffffu, v, o);
    return v;
}
__device__ __forceinline__ void ldsm4(uint32_t* r, uint32_t addr) {
    asm volatile("ldmatrix.sync.aligned.m8n8.x4.shared.b16 {%0,%1,%2,%3}, [%4];"
                 : "=r"(r[0]), "=r"(r[1]), "=r"(r[2]), "=r"(r[3]) : "r"(addr));
}
__device__ __forceinline__ void mma16816(float* c, const uint32_t* a,
                                         uint32_t b0, uint32_t b1) {
    asm volatile(
        "mma.sync.aligned.m16n8k16.row.col.f32.f16.f16.f32 "
        "{%0,%1,%2,%3}, {%4,%5,%6,%7}, {%8,%9}, {%0,%1,%2,%3};"
        : "+f"(c[0]), "+f"(c[1]), "+f"(c[2]), "+f"(c[3])
        : "r"(a[0]), "r"(a[1]), "r"(a[2]), "r"(a[3]), "r"(b0), "r"(b1));
}
__device__ __forceinline__ void cpasync16(uint32_t dst, const __half* src) {
    asm volatile("cp.async.cg.shared.global [%0], [%1], 16;"
                 :: "r"(dst), "l"(__cvta_generic_to_global(src)));
}
#define CP_COMMIT() asm volatile("cp.async.commit_group;" ::: "memory")

__device__ __forceinline__ void split_store(float v, __half* ph, __half* pl) {
    __half h = __float2half(v);
    *ph = h;
    *pl = __float2half(v - __half2float(h));
}
__device__ __forceinline__ float phi_f(float v) {
    return (v > 0.f) ? (v + 1.f) : expf(v);   // elu(v)+1
}

// ---------------------------------------------------------------------------
// mma.sync GEMM (fp16 hi/lo 2-pass): C[:, coloff+n] = f(A[M,K] @ W[K,N])
// ---------------------------------------------------------------------------
#define RS      40
#define SA_HI   0
#define SA_LO   10240
#define SB_HI   20480
#define STG_SZ  30720
#define NSTAGE  3
#define DYN_SMEM (NSTAGE * STG_SZ)     // 92160

template <int EPI, int OUT, bool CONCAT>
__global__ __launch_bounds__(256, 2)
void gemm_as(const __half* __restrict__ Ahi, const __half* __restrict__ Alo,
             const __half* __restrict__ A2hi, const __half* __restrict__ A2lo,
             int lda,
             const __half* __restrict__ Bh,
             int K,
             float* __restrict__ Cf, __half* __restrict__ Chi,
             __half* __restrict__ Clo, int cstride, int coloff, int thresh)
{
    extern __shared__ __align__(128) char sm[];
    const uint32_t sbase = smem_u32(sm);
    const int tid  = threadIdx.x;
    const int lane = tid & 31;
    const int wid  = tid >> 5;
    const int wm   = wid >> 1;
    const int wn   = wid & 1;
    const int m0   = blockIdx.y * 128;
    const int n0   = blockIdx.x * 128;
    const int chunks = K >> 5;

    float acc[2][8][4];
    #pragma unroll
    for (int i = 0; i < 2; i++)
        #pragma unroll
        for (int j = 0; j < 8; j++)
            #pragma unroll
            for (int t = 0; t < 4; t++) acc[i][j][t] = 0.f;

    const int car = tid >> 2;
    const int cas = tid & 3;

    auto issue = [&](int c) {
        const uint32_t stg = sbase + (c % NSTAGE) * STG_SZ;
        const int k0 = c * 32;
        const __half* ah = Ahi;
        const __half* al = Alo;
        int koff = k0;
        if (CONCAT && k0 >= 256) { ah = A2hi; al = A2lo; koff = k0 - 256; }
        #pragma unroll
        for (int i = 0; i < 2; i++) {
            int row = car + i * 64;
            uint32_t doff = (uint32_t)(row * RS + cas * 8) * 2;
            size_t agoff = (size_t)(m0 + row) * lda + koff + cas * 8;
            cpasync16(stg + SA_HI + doff, ah + agoff);
            cpasync16(stg + SA_LO + doff, al + agoff);
            size_t bgoff = (size_t)(n0 + row) * K + k0 + cas * 8;
            cpasync16(stg + SB_HI + doff, Bh + bgoff);
        }
    };

    issue(0); CP_COMMIT();
    if (chunks > 1) { issue(1); CP_COMMIT(); }

    const int arow = wm * 32 + (lane & 15);
    const int ako  = (lane >> 4) << 3;
    const int brow = wn * 64 + ((lane >> 4) << 3) + (lane & 7);
    const int bko  = ((lane >> 3) & 1) << 3;

    for (int c = 0; c < chunks; c++) {
        if (c + 2 < chunks) {
            issue(c + 2); CP_COMMIT();
            asm volatile("cp.async.wait_group 2;" ::: "memory");
        } else if (c + 1 < chunks) {
            asm volatile("cp.async.wait_group 1;" ::: "memory");
        } else {
            asm volatile("cp.async.wait_group 0;" ::: "memory");
        }
        __syncthreads();

        const uint32_t stg = sbase + (c % NSTAGE) * STG_SZ;

        #pragma unroll
        for (int ks = 0; ks < 2; ks++) {
            const int ko = ks * 16;
            uint32_t ah[2][4], al[2][4], bf[4][4];
            #pragma unroll
            for (int mt = 0; mt < 2; mt++) {
                uint32_t ad = stg + SA_HI + (uint32_t)((arow + mt * 16) * RS + ko + ako) * 2;
                ldsm4(ah[mt], ad);
                ldsm4(al[mt], ad + (SA_LO - SA_HI));
            }
            #pragma unroll
            for (int g = 0; g < 4; g++) {
                uint32_t bd = stg + SB_HI + (uint32_t)((brow + g * 16) * RS + ko + bko) * 2;
                ldsm4(bf[g], bd);
            }
            #pragma unroll
            for (int mt = 0; mt < 2; mt++)
                #pragma unroll
                for (int g = 0; g < 4; g++) {
                    mma16816(acc[mt][g * 2 + 0], ah[mt], bf[g][0], bf[g][1]);
                    mma16816(acc[mt][g * 2 + 1], ah[mt], bf[g][2], bf[g][3]);
                }
            #pragma unroll
            for (int mt = 0; mt < 2; mt++)
                #pragma unroll
                for (int g = 0; g < 4; g++) {
                    mma16816(acc[mt][g * 2 + 0], al[mt], bf[g][0], bf[g][1]);
                    mma16816(acc[mt][g * 2 + 1], al[mt], bf[g][2], bf[g][3]);
                }
        }
        __syncthreads();
    }

    const int gp = lane >> 2;
    const int tq = lane & 3;
    #pragma unroll
    for (int mt = 0; mt < 2; mt++) {
        #pragma unroll
        for (int nt = 0; nt < 8; nt++) {
            float* cc = acc[mt][nt];
            int lcol = n0 + wn * 64 + nt * 8 + tq * 2;
            bool dophi = (EPI == 3) && (lcol < thresh);
            #pragma unroll
            for (int t = 0; t < 4; t++) {
                float v = cc[t];
                if (EPI == 2) v = fmaxf(v, 0.f);
                else if (EPI == 3 && dophi) v = phi_f(v);
                cc[t] = v;
            }
            size_t row = (size_t)(m0 + wm * 32 + mt * 16 + gp);
            int col = coloff + lcol;
            if (OUT == 0) {
                *(float2*)(Cf + row * cstride + col)       = make_float2(cc[0], cc[1]);
                *(float2*)(Cf + (row + 8) * cstride + col) = make_float2(cc[2], cc[3]);
            } else {
                #pragma unroll
                for (int rr = 0; rr < 2; rr++) {
                    size_t o = (row + rr * 8) * cstride + col;
                    float v0 = cc[rr * 2 + 0], v1 = cc[rr * 2 + 1];
                    __half h0 = __float2half(v0);
                    __half h1 = __float2half(v1);
                    __half2 hh = __halves2half2(h0, h1);
                    __half2 ll = __halves2half2(
                        __float2half(v0 - __half2float(h0)),
                        __float2half(v1 - __half2float(h1)));
                    *(uint32_t*)(Chi + o) = *(uint32_t*)&hh;
                    *(uint32_t*)(Clo + o) = *(uint32_t*)&ll;
                }
            }
        }
    }
}

// ---------------------------------------------------------------------------
__global__ void prep_w(const float* __restrict__ W, int Kd, int Nd,
                       __half* __restrict__ hi)
{
    int idx = blockIdx.x * blockDim.x + threadIdx.x;
    if (idx >= Kd * Nd) return;
    int n = idx / Kd;
    int k = idx - n * Kd;
    hi[idx] = __float2half(W[(size_t)k * Nd + n]);
}

__global__ __launch_bounds__(256)
void classify_kernel(const float* __restrict__ fwp, const float* __restrict__ proto,
                     float* __restrict__ out_fp, float* __restrict__ out_clsf,
                     int* __restrict__ cls)
{
    __shared__ float sp[NPROT][CDIM];
    int tid = threadIdx.x;
    #pragma unroll
    for (int i = 0; i < 8; i++) {
        int idx = tid + i * 256;
        sp[idx >> 8][idx & 255] = proto[idx];
    }
    __syncthreads();

    int tok = blockIdx.x * 8 + (tid >> 5);
    int lane = tid & 31;
    const float* f = fwp + (size_t)tok * CDIM;

    float acc[NPROT];
    #pragma unroll
    for (int p = 0; p < NPROT; p++) acc[p] = 0.f;
    #pragma unroll
    for (int i = 0; i < 8; i++) {
        float x = f[lane + i * 32];
        #pragma unroll
        for (int p = 0; p < NPROT; p++) acc[p] += x * sp[p][lane + i * 32];
    }
    #pragma unroll
    for (int p = 0; p < NPROT; p++) acc[p] = warp_sum(acc[p]);

    if (lane < NPROT) out_fp[(size_t)tok * NPROT + lane] = acc[lane];
    if (lane == 0) {
        int best = 0; float bv = acc[0];
        #pragma unroll
        for (int p = 1; p < NPROT; p++) if (acc[p] > bv) { bv = acc[p]; best = p; }
        cls[tok] = best;
        out_clsf[tok] = (float)best;
    }
}

__global__ void build_list(const int* __restrict__ cls, const int* __restrict__ mask,
                           int* __restrict__ list, int* __restrict__ cnt)
{
    int g = blockIdx.x;
    int b = g >> 3, c = g & 7;
    int lane = threadIdx.x;
    const int* cb = cls + b * LTOK;
    const int* mb = mask + b * LTOK;
    int base = g * LTOK;
    int count = 0;
    for (int s0 = 0; s0 < LTOK; s0 += 32) {
        int s = s0 + lane;
        bool hit = (cb[s] == c) && (mb[s] != 0);
        unsigned m = __ballot_sync(0xffffffffu, hit);
        if (hit) list[base + count + __popc(m & ((1u << lane) - 1u))] = s;
        count += __popc(m);
    }
    if (lane == 0) cnt[g] = count;
}

__global__ __launch_bounds__(256)
void stats_kernel(const float* __restrict__ QKV,
                  const int* __restrict__ list, const int* __restrict__ cnt,
                  float* __restrict__ KV, float* __restrict__ KS)
{
    __shared__ float sk[32][33];
    __shared__ float sv[32][33];
    __shared__ int   st[32];

    int bid = blockIdx.x;
    int h = bid & 7;
    int c = (bid >> 3) & 7;
    int b = bid >> 6;
    int g = b * 8 + c;

    int tid = threadIdx.x;
    int d  = tid >> 3;
    int e0 = (tid & 7) * 4;

    float a0 = 0.f, a1 = 0.f, a2 = 0.f, a3 = 0.f;
    float ssum = 0.f;

    const float* Kb = QKV + (size_t)b * LTOK * QKVS + 256 + h * DHEAD;
    const float* Vb = QKV + (size_t)b * LTOK * QKVS + 512 + h * DHEAD;
    int n = cnt[g];
    int base = g * LTOK;

    for (int i0 = 0; i0 < n; i0 += 32) {
        if (tid < 32) st[tid] = (i0 + tid < n) ? list[base + i0 + tid] : -1;
        __syncthreads();
        #pragma unroll
        for (int i = 0; i < 4; i++) {
            int idx = tid + i * 256;
            int s = idx >> 5;
            int dd = idx & 31;
            int t = st[s];
            float kk = 0.f, vv = 0.f;
            if (t >= 0) {
                kk = Kb[(size_t)t * QKVS + dd];
                vv = Vb[(size_t)t * QKVS + dd];
            }
            sk[s][dd] = kk;
            sv[s][dd] = vv;
        }
        __syncthreads();
        #pragma unroll
        for (int s = 0; s < 32; s++) {
            float kd = sk[s][d];
            a0 += kd * sv[s][e0 + 0];
            a1 += kd * sv[s][e0 + 1];
            a2 += kd * sv[s][e0 + 2];
            a3 += kd * sv[s][e0 + 3];
        }
        if (tid < 32) {
            #pragma unroll
            for (int s = 0; s < 32; s++) ssum += sk[s][tid];
        }
        __syncthreads();
    }

    size_t o = ((((size_t)b * NPROT + c) * HEADS + h) * DHEAD + d) * DHEAD + e0;
    KV[o + 0] = a0; KV[o + 1] = a1; KV[o + 2] = a2; KV[o + 3] = a3;
    if (tid < 32) KS[(((size_t)b * NPROT + c) * HEADS + h) * DHEAD + tid] = ssum;
}

// ---------------------------------------------------------------------------
// Apply: 8 token-chunks per (b,c) -> 512 blocks; kv/ks in SMEM.
// ---------------------------------------------------------------------------
#define APPLY_CHUNKS 8
__global__ __launch_bounds__(256)
void apply_kernel(const float* __restrict__ QKV, const float* __restrict__ KV,
                  const float* __restrict__ KS, const int* __restrict__ list,
                  const int* __restrict__ cnt,
                  __half* __restrict__ MH, __half* __restrict__ ML)
{
    __shared__ float skv[HEADS][DHEAD][DHEAD];
    __shared__ float sks[HEADS][DHEAD];

    int chunk = blockIdx.x & (APPLY_CHUNKS - 1);
    int g = blockIdx.x / APPLY_CHUNKS;    // b*8 + c
    int b = g >> 3;
    int tid = threadIdx.x;
    int w = tid >> 5, lane = tid & 31;

    for (int i = tid; i < HEADS * DHEAD * DHEAD; i += 256)
        skv[i >> 10][(i >> 5) & 31][i & 31] = KV[(size_t)g * HEADS * DHEAD * DHEAD + i];
    for (int i = tid; i < HEADS * DHEAD; i += 256)
        sks[i >> 5][i & 31] = KS[(size_t)g * HEADS * DHEAD + i];
    __syncthreads();

    int n = cnt[g];
    int lo = (n * chunk) / APPLY_CHUNKS;
    int hi = (n * (chunk + 1)) / APPLY_CHUNKS;
    int base = g * LTOK;

    for (int i0 = lo; i0 < hi; i0 += 8) {
        int ii = i0 + w;
        if (ii < hi) {
            int t = list[base + ii];
            const float* qrow = QKV + ((size_t)b * LTOK + t) * QKVS;
            size_t moff = ((size_t)b * LTOK + t) * CDIM;
            #pragma unroll
            for (int h = 0; h < HEADS; h++) {
                float qd = qrow[h * 32 + lane];
                float den = warp_sum(qd * sks[h][lane]) + EPS_ATTN;
                float num = 0.f;
                #pragma unroll
                for (int dd = 0; dd < 32; dd++)
                    num += __shfl_sync(0xffffffffu, qd, dd) * skv[h][dd][lane];
                float m = num / den;
                split_store(m, MH + moff + h * 32 + lane, ML + moff + h * 32 + lane);
            }
        }
    }
}

__global__ __launch_bounds__(256)
void ln_kernel(const float* __restrict__ X, const float* __restrict__ g,
               const float* __restrict__ b,
               __half* __restrict__ YH, __half* __restrict__ YL)
{
    int tok = blockIdx.x * 8 + (threadIdx.x >> 5);
    int lane = threadIdx.x & 31;
    const float* x = X + (size_t)tok * CDIM;
    float v[8], s = 0.f;
    #pragma unroll
    for (int i = 0; i < 8; i++) { v[i] = x[i * 32 + lane]; s += v[i]; }
    float mean = warp_sum(s) * (1.f / 256.f);
    float s2 = 0.f;
    #pragma unroll
    for (int i = 0; i < 8; i++) { float dd = v[i] - mean; s2 += dd * dd; }
    float rs = rsqrtf(warp_sum(s2) * (1.f / 256.f) + EPS_LN);
    size_t roff = (size_t)tok * CDIM;
    #pragma unroll
    for (int i = 0; i < 8; i++) {
        int cc = i * 32 + lane;
        float y = (v[i] - mean) * rs * g[cc] + b[cc];
        split_store(y, YH + roff + cc, YL + roff + cc);
    }
}

__global__ __launch_bounds__(256)
void final_kernel(const float* __restrict__ Z, const float* __restrict__ g,
                  const float* __restrict__ b, const int* __restrict__ mask,
                  float* __restrict__ X,
                  __half* __restrict__ XH, __half* __restrict__ XL)
{
    int tok = blockIdx.x * 8 + (threadIdx.x >> 5);
    int lane = threadIdx.x & 31;
    if (mask[tok] == 0) return;
    const float* z = Z + (size_t)tok * CDIM;
    float v[8], s = 0.f;
    #pragma unroll
    for (int i = 0; i < 8; i++) { v[i] = z[i * 32 + lane]; s += v[i]; }
    float mean = warp_sum(s) * (1.f / 256.f);
    float s2 = 0.f;
    #pragma unroll
    for (int i = 0; i < 8; i++) { float dd = v[i] - mean; s2 += dd * dd; }
    float rs = rsqrtf(warp_sum(s2) * (1.f / 256.f) + EPS_LN);
    size_t roff = (size_t)tok * CDIM;
    float* x = X + roff;
    #pragma unroll
    for (int i = 0; i < 8; i++) {
        int cc = i * 32 + lane;
        float xn = x[cc] + (v[i] - mean) * rs * g[cc] + b[cc];
        x[cc] = xn;
        split_store(xn, XH + roff + cc, XL + roff + cc);
    }
}

__global__ void copy_split_kernel(const float* __restrict__ s, float* __restrict__ d,
                                  __half* __restrict__ dh,
                                  __half* __restrict__ dl, int n)
{
    int i = blockIdx.x * blockDim.x + threadIdx.x;
    int stride = gridDim.x * blockDim.x;
    for (; i < n; i += stride) {
        float v = s[i];
        d[i] = v;
        split_store(v, dh + i, dl + i);
    }
}
__global__ void copy_kernel(const float* __restrict__ s, float* __restrict__ d, int n)
{
    int i = blockIdx.x * blockDim.x + threadIdx.x;
    int stride = gridDim.x * blockDim.x;
    for (; i < n; i += stride) d[i] = s[i];
}

// ---------------------------------------------------------------------------
// Host orchestration
// ---------------------------------------------------------------------------
struct Bufs {
    float *qkv, *t, *kv, *ks;
    __half *mh, *ml, *hh, *hl;
};

#define MODE_SELF   0
#define MODE_CROSS  1
#define MODE_KVONLY 2

static void launch_q(cudaStream_t st, const __half* xh, const __half* xl,
                     const __half* wh, const Bufs& B)
{
    gemm_as<3, 0, false><<<dim3(2, NTOK / 128), 256, DYN_SMEM, st>>>(
        xh, xl, nullptr, nullptr, CDIM, wh + WOFF_QKV, 256,
        B.qkv, nullptr, nullptr, QKVS, 0, 256);
}

static void run_layer(cudaStream_t st, int mode,
                      float* x, __half* xh, __half* xl,
                      const __half* sh, const __half* sl,
                      const int* listx, const int* cntx,
                      const int* listsrc, const int* cntsrc,
                      const int* maskx,
                      const __half* wh,
                      const float* gg1, const float* bb1,
                      const float* gg2, const float* bb2,
                      const Bufs& B, cudaEvent_t kv_done)
{
    dim3 blk(256);
    const int MT = NTOK / 128;

    if (mode == MODE_SELF) {
        gemm_as<3, 0, false><<<dim3(6, MT), blk, DYN_SMEM, st>>>(xh, xl, nullptr, nullptr,
            CDIM, wh + WOFF_QKV, 256, B.qkv, nullptr, nullptr, QKVS, 0, 512);
    } else {
        if (mode == MODE_CROSS) {
            gemm_as<3, 0, false><<<dim3(2, MT), blk, DYN_SMEM, st>>>(xh, xl, nullptr, nullptr,
                CDIM, wh + WOFF_QKV, 256, B.qkv, nullptr, nullptr, QKVS, 0, 256);
        }
        gemm_as<3, 0, false><<<dim3(4, MT), blk, DYN_SMEM, st>>>(sh, sl, nullptr, nullptr,
            CDIM, wh + WOFF_QKV + 256 * 256, 256, B.qkv, nullptr, nullptr, QKVS, 256, 256);
        if (kv_done) cudaEventRecord(kv_done, st);
    }

    stats_kernel<<<BATCH * NPROT * HEADS, blk, 0, st>>>(B.qkv, listsrc, cntsrc, B.kv, B.ks);
    apply_kernel<<<BATCH * NPROT * APPLY_CHUNKS, blk, 0, st>>>(B.qkv, B.kv, B.ks,
        listx, cntx, B.mh, B.ml);

    gemm_as<0, 0, false><<<dim3(2, MT), blk, DYN_SMEM, st>>>(B.mh, B.ml, nullptr, nullptr,
        CDIM, wh + WOFF_M, 256, B.t, nullptr, nullptr, CDIM, 0, 0);
    ln_kernel<<<NTOK / 8, blk, 0, st>>>(B.t, gg1, bb1, B.mh, B.ml);

    gemm_as<2, 1, true ><<<dim3(4, MT), blk, DYN_SMEM, st>>>(xh, xl, B.mh, B.ml,
        CDIM, wh + WOFF_1, 512, nullptr, B.hh, B.hl, 2 * CDIM, 0, 0);
    gemm_as<0, 0, false><<<dim3(2, MT), blk, DYN_SMEM, st>>>(B.hh, B.hl, nullptr, nullptr,
        2 * CDIM, wh + WOFF_2, 512, B.t, nullptr, nullptr, CDIM, 0, 0);
    final_kernel<<<NTOK / 8, blk, 0, st>>>(B.t, gg2, bb2, maskx, x, xh, xl);
}

// Streams/events created ONCE (first call = correctness run, before the
// harness takes its pre-capture memory baseline). Reused on every call, so
// nothing is allocated during capture/replay and the work per call is
// identical.
static cudaStream_t s_sa = nullptr;
static cudaStream_t s_sb = nullptr;
static cudaEvent_t  s_ev[10];

extern "C" void kernel_launch(void* const* d_in, const int* in_sizes, int n_in,
                              void* d_out, int out_size)
{
    const float* feat0 = (const float*)d_in[0];
    const float* feat1 = (const float*)d_in[1];
    const int*   mask0 = (const int*)  d_in[2];
    const int*   mask1 = (const int*)  d_in[3];
    const float* f0wp  = (const float*)d_in[4];
    const float* f1wp  = (const float*)d_in[5];
    const float* proto = (const float*)d_in[6];
    const float* Wq    = (const float*)d_in[7];
    const float* Wk    = (const float*)d_in[8];
    const float* Wv    = (const float*)d_in[9];
    const float* Wm    = (const float*)d_in[10];
    const float* W1    = (const float*)d_in[11];
    const float* W2    = (const float*)d_in[12];
    const float* G1    = (const float*)d_in[13];
    const float* B1p   = (const float*)d_in[14];
    const float* G2    = (const float*)d_in[15];
    const float* B2p   = (const float*)d_in[16];

    if (!s_sa) {
        cudaStreamCreateWithFlags(&s_sa, cudaStreamNonBlocking);
        cudaStreamCreateWithFlags(&s_sb, cudaStreamNonBlocking);
        for (int i = 0; i < 10; i++)
            cudaEventCreateWithFlags(&s_ev[i], cudaEventDisableTiming);
        cudaFuncSetAttribute(gemm_as<0, 0, false>, cudaFuncAttributeMaxDynamicSharedMemorySize, DYN_SMEM);
        cudaFuncSetAttribute(gemm_as<3, 0, false>, cudaFuncAttributeMaxDynamicSharedMemorySize, DYN_SMEM);
        cudaFuncSetAttribute(gemm_as<2, 1, true >, cudaFuncAttributeMaxDynamicSharedMemorySize, DYN_SMEM);
    }
    cudaStream_t sa = s_sa, sb = s_sb;
    cudaEvent_t* ev = s_ev;

    float* out = (float*)d_out;
    float* x0     = out + OF_F0;
    float* x1     = out + OF_F1;
    float* cls0f  = out + OF_C0;
    float* cls1f  = out + OF_C1;
    float* f0p    = out + OF_F0P;
    float* f1p    = out + OF_F1P;
    float* protoO = out + OF_PROT;

    Bufs BA, BB;
    int *c0, *c1, *l0, *l1, *n0, *n1;
    __half *wh, *x0h, *x0l, *x1h, *x1l;
    cudaGetSymbolAddress((void**)&BA.qkv, g_qkvA);
    cudaGetSymbolAddress((void**)&BA.t,   g_tA);
    cudaGetSymbolAddress((void**)&BA.kv,  g_kvA);
    cudaGetSymbolAddress((void**)&BA.ks,  g_ksA);
    cudaGetSymbolAddress((void**)&BA.mh,  g_mhA);
    cudaGetSymbolAddress((void**)&BA.ml,  g_mlA);
    cudaGetSymbolAddress((void**)&BA.hh,  g_hhA);
    cudaGetSymbolAddress((void**)&BA.hl,  g_hlA);
    cudaGetSymbolAddress((void**)&BB.qkv, g_qkvB);
    cudaGetSymbolAddress((void**)&BB.t,   g_tB);
    cudaGetSymbolAddress((void**)&BB.kv,  g_kvB);
    cudaGetSymbolAddress((void**)&BB.ks,  g_ksB);
    cudaGetSymbolAddress((void**)&BB.mh,  g_mhB);
    cudaGetSymbolAddress((void**)&BB.ml,  g_mlB);
    cudaGetSymbolAddress((void**)&BB.hh,  g_hhB);
    cudaGetSymbolAddress((void**)&BB.hl,  g_hlB);
    cudaGetSymbolAddress((void**)&c0,  g_cls0);
    cudaGetSymbolAddress((void**)&c1,  g_cls1);
    cudaGetSymbolAddress((void**)&l0,  g_list0);
    cudaGetSymbolAddress((void**)&l1,  g_list1);
    cudaGetSymbolAddress((void**)&n0,  g_cnt0);
    cudaGetSymbolAddress((void**)&n1,  g_cnt1);
    cudaGetSymbolAddress((void**)&wh,  g_wh);
    cudaGetSymbolAddress((void**)&x0h, g_x0h);
    cudaGetSymbolAddress((void**)&x0l, g_x0l);
    cudaGetSymbolAddress((void**)&x1h, g_x1h);
    cudaGetSymbolAddress((void**)&x1l, g_x1l);

    // Fork from the (capture-origin) default stream.
    cudaEventRecord(ev[0], 0);
    cudaStreamWaitEvent(sa, ev[0], 0);
    cudaStreamWaitEvent(sb, ev[0], 0);

    // ---- Init (A: feat0 chain; B: feat1 chain + weight prep) ----
    copy_split_kernel<<<2048, 256, 0, sa>>>(feat0, x0, x0h, x0l, NTOK * CDIM);
    classify_kernel<<<NTOK / 8, 256, 0, sa>>>(f0wp, proto, f0p, cls0f, c0);
    build_list<<<BATCH * NPROT, 32, 0, sa>>>(c0, mask0, l0, n0);

    copy_split_kernel<<<2048, 256, 0, sb>>>(feat1, x1, x1h, x1l, NTOK * CDIM);
    copy_kernel<<<8, 256, 0, sb>>>(proto, protoO, NPROT * CDIM);
    classify_kernel<<<NTOK / 8, 256, 0, sb>>>(f1wp, proto, f1p, cls1f, c1);
    build_list<<<BATCH * NPROT, 32, 0, sb>>>(c1, mask1, l1, n1);
    for (int i = 0; i < NLAYER; i++) {
        __half* hb = wh + (size_t)i * WLSZ;
        prep_w<<<(65536 + 255) / 256, 256, 0, sb>>>(Wq + (size_t)i * 65536, 256, 256, hb + WOFF_QKV);
        prep_w<<<(65536 + 255) / 256, 256, 0, sb>>>(Wk + (size_t)i * 65536, 256, 256, hb + WOFF_QKV + 256 * 256);
        prep_w<<<(65536 + 255) / 256, 256, 0, sb>>>(Wv + (size_t)i * 65536, 256, 256, hb + WOFF_QKV + 512 * 256);
        prep_w<<<(65536 + 255) / 256, 256, 0, sb>>>(Wm + (size_t)i * 65536, 256, 256, hb + WOFF_M);
        prep_w<<<(262144 + 255) / 256, 256, 0, sb>>>(W1 + (size_t)i * 262144, 512, 512, hb + WOFF_1);
        prep_w<<<(131072 + 255) / 256, 256, 0, sb>>>(W2 + (size_t)i * 131072, 512, 256, hb + WOFF_2);
    }
    cudaEventRecord(ev[1], sb);           // B init done (weights ready)
    cudaStreamWaitEvent(sa, ev[1], 0);

    const __half* wl0 = wh;
    const __half* wl1 = wh + (size_t)1 * WLSZ;
    const __half* wl2 = wh + (size_t)2 * WLSZ;
    const __half* wl3 = wh + (size_t)3 * WLSZ;

    // ---- L0: self-self (concurrent) ----
    run_layer(sa, MODE_SELF, x0, x0h, x0l, x0h, x0l, l0, n0, l0, n0, mask0,
              wl0, G1, B1p, G2, B2p, BA, nullptr);
    run_layer(sb, MODE_SELF, x1, x1h, x1l, x1h, x1l, l1, n1, l1, n1, mask1,
              wl0, G1, B1p, G2, B2p, BB, nullptr);
    cudaEventRecord(ev[2], sb);           // L0-B done
    cudaStreamWaitEvent(sa, ev[2], 0);

    // ---- L1: cross (app1 on A; app2-q overlapped on B) ----
    launch_q(sb, x1h, x1l, wl1, BB);      // app2 q (depends only on x1)
    run_layer(sa, MODE_CROSS, x0, x0h, x0l, x1h, x1l, l0, n0, l1, n1, mask0,
              wl1, G1 + CDIM, B1p + CDIM, G2 + CDIM, B2p + CDIM, BA, nullptr);
    cudaEventRecord(ev[3], sa);           // app1 done (x0 updated)
    cudaStreamWaitEvent(sb, ev[3], 0);
    run_layer(sb, MODE_KVONLY, x1, x1h, x1l, x0h, x0l, l1, n1, l0, n0, mask1,
              wl1, G1 + CDIM, B1p + CDIM, G2 + CDIM, B2p + CDIM, BB, ev[4]);
    cudaStreamWaitEvent(sa, ev[4], 0);    // A may overwrite x0h after B's kv read

    // ---- L2: self-self (concurrent) ----
    run_layer(sa, MODE_SELF, x0, x0h, x0l, x0h, x0l, l0, n0, l0, n0, mask0,
              wl2, G1 + 2 * CDIM, B1p + 2 * CDIM, G2 + 2 * CDIM, B2p + 2 * CDIM, BA, nullptr);
    run_layer(sb, MODE_SELF, x1, x1h, x1l, x1h, x1l, l1, n1, l1, n1, mask1,
              wl2, G1 + 2 * CDIM, B1p + 2 * CDIM, G2 + 2 * CDIM, B2p + 2 * CDIM, BB, nullptr);
    cudaEventRecord(ev[5], sb);           // L2-B done
    cudaStreamWaitEvent(sa, ev[5], 0);

    // ---- L3: cross ----
    launch_q(sb, x1h, x1l, wl3, BB);
    run_layer(sa, MODE_CROSS, x0, x0h, x0l, x1h, x1l, l0, n0, l1, n1, mask0,
              wl3, G1 + 3 * CDIM, B1p + 3 * CDIM, G2 + 3 * CDIM, B2p + 3 * CDIM, BA, nullptr);
    cudaEventRecord(ev[6], sa);           // app1 done
    cudaStreamWaitEvent(sb, ev[6], 0);
    run_layer(sb, MODE_KVONLY, x1, x1h, x1l, x0h, x0l, l1, n1, l0, n0, mask1,
              wl3, G1 + 3 * CDIM, B1p + 3 * CDIM, G2 + 3 * CDIM, B2p + 3 * CDIM, BB, nullptr);

    // ---- Join back to default stream ----
    cudaEventRecord(ev[7], sa);
    cudaEventRecord(ev[8], sb);
    cudaStreamWaitEvent(0, ev[7], 0);
    cudaStreamWaitEvent(0, ev[8], 0);

    (void)in_sizes; (void)n_in; (void)out_size;
}

// round 9
// speedup vs baseline: 2.4163x; 1.4532x over previous
#include <cuda_runtime.h>
#include <cuda_fp16.h>
#include <math.h>
#include <stdint.h>

// ---------------------------------------------------------------------------
// Problem constants
// ---------------------------------------------------------------------------
#define BATCH 8
#define LTOK  4800
#define CDIM  256
#define HEADS 8
#define DHEAD 32
#define NPROT 8
#define NLAYER 4
#define NTOK  (BATCH * LTOK)          // 38400
#define EPS_ATTN 1e-6f
#define EPS_LN   1e-5f
#define QKVS  768                      // fused q|k|v row stride

// Output layout (floats), tuple order:
// feat0, feat1, class0, class1, f0p, f1p, prototype
#define OF_F0    0
#define OF_F1    (NTOK * CDIM)
#define OF_C0    (2 * NTOK * CDIM)
#define OF_C1    (OF_C0 + NTOK)
#define OF_F0P   (OF_C1 + NTOK)
#define OF_F1P   (OF_F0P + NTOK * NPROT)
#define OF_PROT  (OF_F1P + NTOK * NPROT)

// ---------------------------------------------------------------------------
// Device scratch (two sets: stream A / stream B). All activation buffers are
// COMPACTED over valid tokens (dense rows 0..nv-1).
// ---------------------------------------------------------------------------
__device__ __align__(16) float g_qkvA[NTOK * QKVS];
__device__ __align__(16) float g_qkvB[NTOK * QKVS];
__device__ __align__(16) float g_tA  [NTOK * CDIM];
__device__ __align__(16) float g_tB  [NTOK * CDIM];
__device__ __align__(16) float g_kvA [BATCH * NPROT * HEADS * DHEAD * DHEAD];
__device__ __align__(16) float g_kvB [BATCH * NPROT * HEADS * DHEAD * DHEAD];
__device__ __align__(16) float g_ksA [BATCH * NPROT * HEADS * DHEAD];
__device__ __align__(16) float g_ksB [BATCH * NPROT * HEADS * DHEAD];
__device__ __align__(16) __half g_mhA[NTOK * CDIM];
__device__ __align__(16) __half g_mlA[NTOK * CDIM];
__device__ __align__(16) __half g_mhB[NTOK * CDIM];
__device__ __align__(16) __half g_mlB[NTOK * CDIM];
__device__ __align__(16) __half g_hhA[NTOK * 2 * CDIM];
__device__ __align__(16) __half g_hlA[NTOK * 2 * CDIM];
__device__ __align__(16) __half g_hhB[NTOK * 2 * CDIM];
__device__ __align__(16) __half g_hlB[NTOK * 2 * CDIM];

__device__ int   g_cls0[NTOK];
__device__ int   g_cls1[NTOK];
__device__ int   g_list0[BATCH * NPROT * LTOK];
__device__ int   g_list1[BATCH * NPROT * LTOK];
__device__ int   g_cnt0[BATCH * NPROT];
__device__ int   g_cnt1[BATCH * NPROT];

// Valid-token compaction
__device__ int   g_vtok0[NTOK];
__device__ int   g_vtok1[NTOK];
__device__ int   g_cmap0[NTOK];
__device__ int   g_cmap1[NTOK];
__device__ int   g_vcnt0;
__device__ int   g_vcnt1;

// fp16 hi/lo feature buffers (compacted)
__device__ __align__(16) __half g_x0h[NTOK * CDIM];
__device__ __align__(16) __half g_x0l[NTOK * CDIM];
__device__ __align__(16) __half g_x1h[NTOK * CDIM];
__device__ __align__(16) __half g_x1l[NTOK * CDIM];

// Transposed fp16 weights per layer: [Wq|Wk|Wv] (768x256), Wm, W1, W2 ([N,K])
#define WOFF_QKV 0
#define WOFF_M   196608
#define WOFF_1   262144
#define WOFF_2   524288
#define WLSZ     655360
__device__ __align__(16) __half g_wh[NLAYER * WLSZ];

// ---------------------------------------------------------------------------
// Helpers
// ---------------------------------------------------------------------------
__device__ __forceinline__ uint32_t smem_u32(const void* p) {
    uint32_t a;
    asm("{ .reg .u64 t; cvta.to.shared.u64 t, %1; cvt.u32.u64 %0, t; }"
        : "=r"(a) : "l"(p));
    return a;
}
__device__ __forceinline__ float warp_sum(float v) {
    #pragma unroll
    for (int o = 16; o; o >>= 1) v += __shfl_xor_sync(0xffffffffu, v, o);
    return v;
}
__device__ __forceinline__ void ldsm4(uint32_t* r, uint32_t addr) {
    asm volatile("ldmatrix.sync.aligned.m8n8.x4.shared.b16 {%0,%1,%2,%3}, [%4];"
                 : "=r"(r[0]), "=r"(r[1]), "=r"(r[2]), "=r"(r[3]) : "r"(addr));
}
__device__ __forceinline__ void mma16816(float* c, const uint32_t* a,
                                         uint32_t b0, uint32_t b1) {
    asm volatile(
        "mma.sync.aligned.m16n8k16.row.col.f32.f16.f16.f32 "
        "{%0,%1,%2,%3}, {%4,%5,%6,%7}, {%8,%9}, {%0,%1,%2,%3};"
        : "+f"(c[0]), "+f"(c[1]), "+f"(c[2]), "+f"(c[3])
        : "r"(a[0]), "r"(a[1]), "r"(a[2]), "r"(a[3]), "r"(b0), "r"(b1));
}
__device__ __forceinline__ void cpasync16(uint32_t dst, const __half* src) {
    asm volatile("cp.async.cg.shared.global [%0], [%1], 16;"
                 :: "r"(dst), "l"(__cvta_generic_to_global(src)));
}
#define CP_COMMIT() asm volatile("cp.async.commit_group;" ::: "memory")

__device__ __forceinline__ void split_store(float v, __half* ph, __half* pl) {
    __half h = __float2half(v);
    *ph = h;
    *pl = __float2half(v - __half2float(h));
}
__device__ __forceinline__ float phi_f(float v) {
    return (v > 0.f) ? (v + 1.f) : expf(v);   // elu(v)+1
}

// ---------------------------------------------------------------------------
// mma.sync GEMM (fp16 hi/lo 2-pass) over COMPACTED rows; CTAs beyond the
// valid-row count exit early (grid stays fixed for graph capture).
// ---------------------------------------------------------------------------
#define RS      40
#define SA_HI   0
#define SA_LO   10240
#define SB_HI   20480
#define STG_SZ  30720
#define NSTAGE  3
#define DYN_SMEM (NSTAGE * STG_SZ)     // 92160

template <int EPI, int OUT, bool CONCAT>
__global__ __launch_bounds__(256, 2)
void gemm_as(const __half* __restrict__ Ahi, const __half* __restrict__ Alo,
             const __half* __restrict__ A2hi, const __half* __restrict__ A2lo,
             int lda,
             const __half* __restrict__ Bh,
             int K,
             float* __restrict__ Cf, __half* __restrict__ Chi,
             __half* __restrict__ Clo, int cstride, int coloff, int thresh,
             const int* __restrict__ nvp)
{
    const int m0 = blockIdx.y * 128;
    if (m0 >= __ldg(nvp)) return;      // compacted-row early exit

    extern __shared__ __align__(128) char sm[];
    const uint32_t sbase = smem_u32(sm);
    const int tid  = threadIdx.x;
    const int lane = tid & 31;
    const int wid  = tid >> 5;
    const int wm   = wid >> 1;
    const int wn   = wid & 1;
    const int n0   = blockIdx.x * 128;
    const int chunks = K >> 5;

    float acc[2][8][4];
    #pragma unroll
    for (int i = 0; i < 2; i++)
        #pragma unroll
        for (int j = 0; j < 8; j++)
            #pragma unroll
            for (int t = 0; t < 4; t++) acc[i][j][t] = 0.f;

    const int car = tid >> 2;
    const int cas = tid & 3;

    auto issue = [&](int c) {
        const uint32_t stg = sbase + (c % NSTAGE) * STG_SZ;
        const int k0 = c * 32;
        const __half* ah = Ahi;
        const __half* al = Alo;
        int koff = k0;
        if (CONCAT && k0 >= 256) { ah = A2hi; al = A2lo; koff = k0 - 256; }
        #pragma unroll
        for (int i = 0; i < 2; i++) {
            int row = car + i * 64;
            uint32_t doff = (uint32_t)(row * RS + cas * 8) * 2;
            size_t agoff = (size_t)(m0 + row) * lda + koff + cas * 8;
            cpasync16(stg + SA_HI + doff, ah + agoff);
            cpasync16(stg + SA_LO + doff, al + agoff);
            size_t bgoff = (size_t)(n0 + row) * K + k0 + cas * 8;
            cpasync16(stg + SB_HI + doff, Bh + bgoff);
        }
    };

    issue(0); CP_COMMIT();
    if (chunks > 1) { issue(1); CP_COMMIT(); }

    const int arow = wm * 32 + (lane & 15);
    const int ako  = (lane >> 4) << 3;
    const int brow = wn * 64 + ((lane >> 4) << 3) + (lane & 7);
    const int bko  = ((lane >> 3) & 1) << 3;

    for (int c = 0; c < chunks; c++) {
        if (c + 2 < chunks) {
            issue(c + 2); CP_COMMIT();
            asm volatile("cp.async.wait_group 2;" ::: "memory");
        } else if (c + 1 < chunks) {
            asm volatile("cp.async.wait_group 1;" ::: "memory");
        } else {
            asm volatile("cp.async.wait_group 0;" ::: "memory");
        }
        __syncthreads();

        const uint32_t stg = sbase + (c % NSTAGE) * STG_SZ;

        #pragma unroll
        for (int ks = 0; ks < 2; ks++) {
            const int ko = ks * 16;
            uint32_t ah[2][4], al[2][4], bf[4][4];
            #pragma unroll
            for (int mt = 0; mt < 2; mt++) {
                uint32_t ad = stg + SA_HI + (uint32_t)((arow + mt * 16) * RS + ko + ako) * 2;
                ldsm4(ah[mt], ad);
                ldsm4(al[mt], ad + (SA_LO - SA_HI));
            }
            #pragma unroll
            for (int g = 0; g < 4; g++) {
                uint32_t bd = stg + SB_HI + (uint32_t)((brow + g * 16) * RS + ko + bko) * 2;
                ldsm4(bf[g], bd);
            }
            #pragma unroll
            for (int mt = 0; mt < 2; mt++)
                #pragma unroll
                for (int g = 0; g < 4; g++) {
                    mma16816(acc[mt][g * 2 + 0], ah[mt], bf[g][0], bf[g][1]);
                    mma16816(acc[mt][g * 2 + 1], ah[mt], bf[g][2], bf[g][3]);
                }
            #pragma unroll
            for (int mt = 0; mt < 2; mt++)
                #pragma unroll
                for (int g = 0; g < 4; g++) {
                    mma16816(acc[mt][g * 2 + 0], al[mt], bf[g][0], bf[g][1]);
                    mma16816(acc[mt][g * 2 + 1], al[mt], bf[g][2], bf[g][3]);
                }
        }
        __syncthreads();
    }

    const int gp = lane >> 2;
    const int tq = lane & 3;
    #pragma unroll
    for (int mt = 0; mt < 2; mt++) {
        #pragma unroll
        for (int nt = 0; nt < 8; nt++) {
            float* cc = acc[mt][nt];
            int lcol = n0 + wn * 64 + nt * 8 + tq * 2;
            bool dophi = (EPI == 3) && (lcol < thresh);
            #pragma unroll
            for (int t = 0; t < 4; t++) {
                float v = cc[t];
                if (EPI == 2) v = fmaxf(v, 0.f);
                else if (EPI == 3 && dophi) v = phi_f(v);
                cc[t] = v;
            }
            size_t row = (size_t)(m0 + wm * 32 + mt * 16 + gp);
            int col = coloff + lcol;
            if (OUT == 0) {
                *(float2*)(Cf + row * cstride + col)       = make_float2(cc[0], cc[1]);
                *(float2*)(Cf + (row + 8) * cstride + col) = make_float2(cc[2], cc[3]);
            } else {
                #pragma unroll
                for (int rr = 0; rr < 2; rr++) {
                    size_t o = (row + rr * 8) * cstride + col;
                    float v0 = cc[rr * 2 + 0], v1 = cc[rr * 2 + 1];
                    __half h0 = __float2half(v0);
                    __half h1 = __float2half(v1);
                    __half2 hh = __halves2half2(h0, h1);
                    __half2 ll = __halves2half2(
                        __float2half(v0 - __half2float(h0)),
                        __float2half(v1 - __half2float(h1)));
                    *(uint32_t*)(Chi + o) = *(uint32_t*)&hh;
                    *(uint32_t*)(Clo + o) = *(uint32_t*)&ll;
                }
            }
        }
    }
}

// ---------------------------------------------------------------------------
__global__ void prep_w(const float* __restrict__ W, int Kd, int Nd,
                       __half* __restrict__ hi)
{
    int idx = blockIdx.x * blockDim.x + threadIdx.x;
    if (idx >= Kd * Nd) return;
    int n = idx / Kd;
    int k = idx - n * Kd;
    hi[idx] = __float2half(W[(size_t)k * Nd + n]);
}

__global__ __launch_bounds__(256)
void classify_kernel(const float* __restrict__ fwp, const float* __restrict__ proto,
                     float* __restrict__ out_fp, float* __restrict__ out_clsf,
                     int* __restrict__ cls)
{
    __shared__ float sp[NPROT][CDIM];
    int tid = threadIdx.x;
    #pragma unroll
    for (int i = 0; i < 8; i++) {
        int idx = tid + i * 256;
        sp[idx >> 8][idx & 255] = proto[idx];
    }
    __syncthreads();

    int tok = blockIdx.x * 8 + (tid >> 5);
    int lane = tid & 31;
    const float* f = fwp + (size_t)tok * CDIM;

    float acc[NPROT];
    #pragma unroll
    for (int p = 0; p < NPROT; p++) acc[p] = 0.f;
    #pragma unroll
    for (int i = 0; i < 8; i++) {
        float x = f[lane + i * 32];
        #pragma unroll
        for (int p = 0; p < NPROT; p++) acc[p] += x * sp[p][lane + i * 32];
    }
    #pragma unroll
    for (int p = 0; p < NPROT; p++) acc[p] = warp_sum(acc[p]);

    if (lane < NPROT) out_fp[(size_t)tok * NPROT + lane] = acc[lane];
    if (lane == 0) {
        int best = 0; float bv = acc[0];
        #pragma unroll
        for (int p = 1; p < NPROT; p++) if (acc[p] > bv) { bv = acc[p]; best = p; }
        cls[tok] = best;
        out_clsf[tok] = (float)best;
    }
}

// ---------------------------------------------------------------------------
// Valid-token compaction: ordered list + inverse map + count (one warp).
// ---------------------------------------------------------------------------
__global__ void build_valid(const int* __restrict__ mask, int* __restrict__ vtok,
                            int* __restrict__ cmap, int* __restrict__ vcnt)
{
    int lane = threadIdx.x;
    int count = 0;
    for (int s0 = 0; s0 < NTOK; s0 += 32) {
        int t = s0 + lane;
        bool hit = mask[t] != 0;
        unsigned m = __ballot_sync(0xffffffffu, hit);
        int idx = count + __popc(m & ((1u << lane) - 1u));
        if (hit) { vtok[idx] = t; cmap[t] = idx; }
        else cmap[t] = -1;
        count += __popc(m);
    }
    if (lane == 0) *vcnt = count;
    for (int i = count + lane; i < NTOK; i += 32) vtok[i] = 0;  // safe tail
}

// Class token lists in COMPACT indices (requires cmap).
__global__ void build_list(const int* __restrict__ cls, const int* __restrict__ mask,
                           const int* __restrict__ cmap,
                           int* __restrict__ list, int* __restrict__ cnt)
{
    int g = blockIdx.x;
    int b = g >> 3, c = g & 7;
    int lane = threadIdx.x;
    const int* cb = cls + b * LTOK;
    const int* mb = mask + b * LTOK;
    int base = g * LTOK;
    int count = 0;
    for (int s0 = 0; s0 < LTOK; s0 += 32) {
        int s = s0 + lane;
        bool hit = (cb[s] == c) && (mb[s] != 0);
        unsigned m = __ballot_sync(0xffffffffu, hit);
        if (hit) list[base + count + __popc(m & ((1u << lane) - 1u))] = cmap[b * LTOK + s];
        count += __popc(m);
    }
    if (lane == 0) cnt[g] = count;
}

// Gather + hi/lo split from full feature into compacted xh/xl.
__global__ void gather_split(const float* __restrict__ feat, const int* __restrict__ vtok,
                             const int* __restrict__ nvp,
                             __half* __restrict__ xh, __half* __restrict__ xl)
{
    int nv = __ldg(nvp);
    int total = nv * CDIM;
    int i = blockIdx.x * blockDim.x + threadIdx.x;
    int stride = gridDim.x * blockDim.x;
    for (; i < total; i += stride) {
        int row = i >> 8, col = i & 255;
        float v = feat[(size_t)__ldg(vtok + row) * CDIM + col];
        split_store(v, xh + i, xl + i);
    }
}

// ---------------------------------------------------------------------------
// Per-class stats via compact token lists. Block per (b,c,h).
// ---------------------------------------------------------------------------
__global__ __launch_bounds__(256)
void stats_kernel(const float* __restrict__ QKV,
                  const int* __restrict__ list, const int* __restrict__ cnt,
                  float* __restrict__ KV, float* __restrict__ KS)
{
    __shared__ float sk[32][33];
    __shared__ float sv[32][33];
    __shared__ int   st[32];

    int bid = blockIdx.x;
    int h = bid & 7;
    int c = (bid >> 3) & 7;
    int b = bid >> 6;
    int g = b * 8 + c;

    int tid = threadIdx.x;
    int d  = tid >> 3;
    int e0 = (tid & 7) * 4;

    float a0 = 0.f, a1 = 0.f, a2 = 0.f, a3 = 0.f;
    float ssum = 0.f;

    const float* Kb = QKV + 256 + h * DHEAD;   // rows are GLOBAL compact indices
    const float* Vb = QKV + 512 + h * DHEAD;
    int n = cnt[g];
    int base = g * LTOK;

    for (int i0 = 0; i0 < n; i0 += 32) {
        if (tid < 32) st[tid] = (i0 + tid < n) ? list[base + i0 + tid] : -1;
        __syncthreads();
        #pragma unroll
        for (int i = 0; i < 4; i++) {
            int idx = tid + i * 256;
            int s = idx >> 5;
            int dd = idx & 31;
            int t = st[s];
            float kk = 0.f, vv = 0.f;
            if (t >= 0) {
                kk = Kb[(size_t)t * QKVS + dd];
                vv = Vb[(size_t)t * QKVS + dd];
            }
            sk[s][dd] = kk;
            sv[s][dd] = vv;
        }
        __syncthreads();
        #pragma unroll
        for (int s = 0; s < 32; s++) {
            float kd = sk[s][d];
            a0 += kd * sv[s][e0 + 0];
            a1 += kd * sv[s][e0 + 1];
            a2 += kd * sv[s][e0 + 2];
            a3 += kd * sv[s][e0 + 3];
        }
        if (tid < 32) {
            #pragma unroll
            for (int s = 0; s < 32; s++) ssum += sk[s][tid];
        }
        __syncthreads();
    }

    size_t o = ((((size_t)b * NPROT + c) * HEADS + h) * DHEAD + d) * DHEAD + e0;
    KV[o + 0] = a0; KV[o + 1] = a1; KV[o + 2] = a2; KV[o + 3] = a3;
    if (tid < 32) KS[(((size_t)b * NPROT + c) * HEADS + h) * DHEAD + tid] = ssum;
}

// ---------------------------------------------------------------------------
// Apply: 8 token-chunks per (b,c); compact q rows; writes msg hi/lo compact.
// ---------------------------------------------------------------------------
#define APPLY_CHUNKS 8
__global__ __launch_bounds__(256)
void apply_kernel(const float* __restrict__ QKV, const float* __restrict__ KV,
                  const float* __restrict__ KS, const int* __restrict__ list,
                  const int* __restrict__ cnt,
                  __half* __restrict__ MH, __half* __restrict__ ML)
{
    __shared__ float skv[HEADS][DHEAD][DHEAD];
    __shared__ float sks[HEADS][DHEAD];

    int chunk = blockIdx.x & (APPLY_CHUNKS - 1);
    int g = blockIdx.x / APPLY_CHUNKS;    // b*8 + c
    int tid = threadIdx.x;
    int w = tid >> 5, lane = tid & 31;

    for (int i = tid; i < HEADS * DHEAD * DHEAD; i += 256)
        skv[i >> 10][(i >> 5) & 31][i & 31] = KV[(size_t)g * HEADS * DHEAD * DHEAD + i];
    for (int i = tid; i < HEADS * DHEAD; i += 256)
        sks[i >> 5][i & 31] = KS[(size_t)g * HEADS * DHEAD + i];
    __syncthreads();

    int n = cnt[g];
    int lo = (n * chunk) / APPLY_CHUNKS;
    int hi = (n * (chunk + 1)) / APPLY_CHUNKS;
    int base = g * LTOK;

    for (int i0 = lo; i0 < hi; i0 += 8) {
        int ii = i0 + w;
        if (ii < hi) {
            int t = list[base + ii];              // compact row
            const float* qrow = QKV + (size_t)t * QKVS;
            size_t moff = (size_t)t * CDIM;
            #pragma unroll
            for (int h = 0; h < HEADS; h++) {
                float qd = qrow[h * 32 + lane];
                float den = warp_sum(qd * sks[h][lane]) + EPS_ATTN;
                float num = 0.f;
                #pragma unroll
                for (int dd = 0; dd < 32; dd++)
                    num += __shfl_sync(0xffffffffu, qd, dd) * skv[h][dd][lane];
                float m = num / den;
                split_store(m, MH + moff + h * 32 + lane, ML + moff + h * 32 + lane);
            }
        }
    }
}

// LayerNorm over compact rows (early exit past nv).
__global__ __launch_bounds__(256)
void ln_kernel(const float* __restrict__ X, const float* __restrict__ g,
               const float* __restrict__ b, const int* __restrict__ nvp,
               __half* __restrict__ YH, __half* __restrict__ YL)
{
    int row = blockIdx.x * 8 + (threadIdx.x >> 5);
    if (row >= __ldg(nvp)) return;
    int lane = threadIdx.x & 31;
    const float* x = X + (size_t)row * CDIM;
    float v[8], s = 0.f;
    #pragma unroll
    for (int i = 0; i < 8; i++) { v[i] = x[i * 32 + lane]; s += v[i]; }
    float mean = warp_sum(s) * (1.f / 256.f);
    float s2 = 0.f;
    #pragma unroll
    for (int i = 0; i < 8; i++) { float dd = v[i] - mean; s2 += dd * dd; }
    float rs = rsqrtf(warp_sum(s2) * (1.f / 256.f) + EPS_LN);
    size_t roff = (size_t)row * CDIM;
    #pragma unroll
    for (int i = 0; i < 8; i++) {
        int cc = i * 32 + lane;
        float y = (v[i] - mean) * rs * g[cc] + b[cc];
        split_store(y, YH + roff + cc, YL + roff + cc);
    }
}

// Final: compact row -> scatter x update via vtok; refresh compact hi/lo.
__global__ __launch_bounds__(256)
void final_kernel(const float* __restrict__ Z, const float* __restrict__ g,
                  const float* __restrict__ b, const int* __restrict__ nvp,
                  const int* __restrict__ vtok, float* __restrict__ X,
                  __half* __restrict__ XH, __half* __restrict__ XL)
{
    int row = blockIdx.x * 8 + (threadIdx.x >> 5);
    if (row >= __ldg(nvp)) return;
    int lane = threadIdx.x & 31;
    const float* z = Z + (size_t)row * CDIM;
    float v[8], s = 0.f;
    #pragma unroll
    for (int i = 0; i < 8; i++) { v[i] = z[i * 32 + lane]; s += v[i]; }
    float mean = warp_sum(s) * (1.f / 256.f);
    float s2 = 0.f;
    #pragma unroll
    for (int i = 0; i < 8; i++) { float dd = v[i] - mean; s2 += dd * dd; }
    float rs = rsqrtf(warp_sum(s2) * (1.f / 256.f) + EPS_LN);
    size_t roff = (size_t)row * CDIM;
    float* x = X + (size_t)__ldg(vtok + row) * CDIM;
    #pragma unroll
    for (int i = 0; i < 8; i++) {
        int cc = i * 32 + lane;
        float xn = x[cc] + (v[i] - mean) * rs * g[cc] + b[cc];
        x[cc] = xn;
        split_store(xn, XH + roff + cc, XL + roff + cc);
    }
}

__global__ void copy_kernel(const float* __restrict__ s, float* __restrict__ d, int n)
{
    int i = blockIdx.x * blockDim.x + threadIdx.x;
    int stride = gridDim.x * blockDim.x;
    for (; i < n; i += stride) d[i] = s[i];
}

// ---------------------------------------------------------------------------
// Host orchestration
// ---------------------------------------------------------------------------
struct Bufs {
    float *qkv, *t, *kv, *ks;
    __half *mh, *ml, *hh, *hl;
};

#define MODE_SELF   0
#define MODE_CROSS  1
#define MODE_KVONLY 2

static void launch_q(cudaStream_t st, const __half* xh, const __half* xl,
                     const __half* wh, const Bufs& B, const int* nvx)
{
    gemm_as<3, 0, false><<<dim3(2, NTOK / 128), 256, DYN_SMEM, st>>>(
        xh, xl, nullptr, nullptr, CDIM, wh + WOFF_QKV, 256,
        B.qkv, nullptr, nullptr, QKVS, 0, 256, nvx);
}

static void run_layer(cudaStream_t st, int mode,
                      float* x, __half* xh, __half* xl,
                      const __half* sh, const __half* sl,
                      const int* listx, const int* cntx,
                      const int* listsrc, const int* cntsrc,
                      const int* nvx, const int* nvsrc, const int* vtokx,
                      const __half* wh,
                      const float* gg1, const float* bb1,
                      const float* gg2, const float* bb2,
                      const Bufs& B, cudaEvent_t kv_done)
{
    dim3 blk(256);
    const int MT = NTOK / 128;

    if (mode == MODE_SELF) {
        gemm_as<3, 0, false><<<dim3(6, MT), blk, DYN_SMEM, st>>>(xh, xl, nullptr, nullptr,
            CDIM, wh + WOFF_QKV, 256, B.qkv, nullptr, nullptr, QKVS, 0, 512, nvx);
    } else {
        if (mode == MODE_CROSS) {
            gemm_as<3, 0, false><<<dim3(2, MT), blk, DYN_SMEM, st>>>(xh, xl, nullptr, nullptr,
                CDIM, wh + WOFF_QKV, 256, B.qkv, nullptr, nullptr, QKVS, 0, 256, nvx);
        }
        gemm_as<3, 0, false><<<dim3(4, MT), blk, DYN_SMEM, st>>>(sh, sl, nullptr, nullptr,
            CDIM, wh + WOFF_QKV + 256 * 256, 256, B.qkv, nullptr, nullptr, QKVS, 256, 256, nvsrc);
        if (kv_done) cudaEventRecord(kv_done, st);
    }

    stats_kernel<<<BATCH * NPROT * HEADS, blk, 0, st>>>(B.qkv, listsrc, cntsrc, B.kv, B.ks);
    apply_kernel<<<BATCH * NPROT * APPLY_CHUNKS, blk, 0, st>>>(B.qkv, B.kv, B.ks,
        listx, cntx, B.mh, B.ml);

    gemm_as<0, 0, false><<<dim3(2, MT), blk, DYN_SMEM, st>>>(B.mh, B.ml, nullptr, nullptr,
        CDIM, wh + WOFF_M, 256, B.t, nullptr, nullptr, CDIM, 0, 0, nvx);
    ln_kernel<<<NTOK / 8, blk, 0, st>>>(B.t, gg1, bb1, nvx, B.mh, B.ml);

    gemm_as<2, 1, true ><<<dim3(4, MT), blk, DYN_SMEM, st>>>(xh, xl, B.mh, B.ml,
        CDIM, wh + WOFF_1, 512, nullptr, B.hh, B.hl, 2 * CDIM, 0, 0, nvx);
    gemm_as<0, 0, false><<<dim3(2, MT), blk, DYN_SMEM, st>>>(B.hh, B.hl, nullptr, nullptr,
        2 * CDIM, wh + WOFF_2, 512, B.t, nullptr, nullptr, CDIM, 0, 0, nvx);
    final_kernel<<<NTOK / 8, blk, 0, st>>>(B.t, gg2, bb2, nvx, vtokx, x, xh, xl);
}

// Streams/events created ONCE (first call = correctness run, before the
// harness takes its pre-capture baseline). Reused every call.
static cudaStream_t s_sa = nullptr;
static cudaStream_t s_sb = nullptr;
static cudaEvent_t  s_ev[10];

extern "C" void kernel_launch(void* const* d_in, const int* in_sizes, int n_in,
                              void* d_out, int out_size)
{
    const float* feat0 = (const float*)d_in[0];
    const float* feat1 = (const float*)d_in[1];
    const int*   mask0 = (const int*)  d_in[2];
    const int*   mask1 = (const int*)  d_in[3];
    const float* f0wp  = (const float*)d_in[4];
    const float* f1wp  = (const float*)d_in[5];
    const float* proto = (const float*)d_in[6];
    const float* Wq    = (const float*)d_in[7];
    const float* Wk    = (const float*)d_in[8];
    const float* Wv    = (const float*)d_in[9];
    const float* Wm    = (const float*)d_in[10];
    const float* W1    = (const float*)d_in[11];
    const float* W2    = (const float*)d_in[12];
    const float* G1    = (const float*)d_in[13];
    const float* B1p   = (const float*)d_in[14];
    const float* G2    = (const float*)d_in[15];
    const float* B2p   = (const float*)d_in[16];

    if (!s_sa) {
        cudaStreamCreateWithFlags(&s_sa, cudaStreamNonBlocking);
        cudaStreamCreateWithFlags(&s_sb, cudaStreamNonBlocking);
        for (int i = 0; i < 10; i++)
            cudaEventCreateWithFlags(&s_ev[i], cudaEventDisableTiming);
        cudaFuncSetAttribute(gemm_as<0, 0, false>, cudaFuncAttributeMaxDynamicSharedMemorySize, DYN_SMEM);
        cudaFuncSetAttribute(gemm_as<3, 0, false>, cudaFuncAttributeMaxDynamicSharedMemorySize, DYN_SMEM);
        cudaFuncSetAttribute(gemm_as<2, 1, true >, cudaFuncAttributeMaxDynamicSharedMemorySize, DYN_SMEM);
    }
    cudaStream_t sa = s_sa, sb = s_sb;
    cudaEvent_t* ev = s_ev;

    float* out = (float*)d_out;
    float* x0     = out + OF_F0;
    float* x1     = out + OF_F1;
    float* cls0f  = out + OF_C0;
    float* cls1f  = out + OF_C1;
    float* f0p    = out + OF_F0P;
    float* f1p    = out + OF_F1P;
    float* protoO = out + OF_PROT;

    Bufs BA, BB;
    int *c0, *c1, *l0, *l1, *n0, *n1;
    int *vt0, *vt1, *cm0, *cm1, *nv0, *nv1;
    __half *wh, *x0h, *x0l, *x1h, *x1l;
    cudaGetSymbolAddress((void**)&BA.qkv, g_qkvA);
    cudaGetSymbolAddress((void**)&BA.t,   g_tA);
    cudaGetSymbolAddress((void**)&BA.kv,  g_kvA);
    cudaGetSymbolAddress((void**)&BA.ks,  g_ksA);
    cudaGetSymbolAddress((void**)&BA.mh,  g_mhA);
    cudaGetSymbolAddress((void**)&BA.ml,  g_mlA);
    cudaGetSymbolAddress((void**)&BA.hh,  g_hhA);
    cudaGetSymbolAddress((void**)&BA.hl,  g_hlA);
    cudaGetSymbolAddress((void**)&BB.qkv, g_qkvB);
    cudaGetSymbolAddress((void**)&BB.t,   g_tB);
    cudaGetSymbolAddress((void**)&BB.kv,  g_kvB);
    cudaGetSymbolAddress((void**)&BB.ks,  g_ksB);
    cudaGetSymbolAddress((void**)&BB.mh,  g_mhB);
    cudaGetSymbolAddress((void**)&BB.ml,  g_mlB);
    cudaGetSymbolAddress((void**)&BB.hh,  g_hhB);
    cudaGetSymbolAddress((void**)&BB.hl,  g_hlB);
    cudaGetSymbolAddress((void**)&c0,  g_cls0);
    cudaGetSymbolAddress((void**)&c1,  g_cls1);
    cudaGetSymbolAddress((void**)&l0,  g_list0);
    cudaGetSymbolAddress((void**)&l1,  g_list1);
    cudaGetSymbolAddress((void**)&n0,  g_cnt0);
    cudaGetSymbolAddress((void**)&n1,  g_cnt1);
    cudaGetSymbolAddress((void**)&vt0, g_vtok0);
    cudaGetSymbolAddress((void**)&vt1, g_vtok1);
    cudaGetSymbolAddress((void**)&cm0, g_cmap0);
    cudaGetSymbolAddress((void**)&cm1, g_cmap1);
    cudaGetSymbolAddress((void**)&nv0, g_vcnt0);
    cudaGetSymbolAddress((void**)&nv1, g_vcnt1);
    cudaGetSymbolAddress((void**)&wh,  g_wh);
    cudaGetSymbolAddress((void**)&x0h, g_x0h);
    cudaGetSymbolAddress((void**)&x0l, g_x0l);
    cudaGetSymbolAddress((void**)&x1h, g_x1h);
    cudaGetSymbolAddress((void**)&x1l, g_x1l);

    // Fork from the (capture-origin) default stream.
    cudaEventRecord(ev[0], 0);
    cudaStreamWaitEvent(sa, ev[0], 0);
    cudaStreamWaitEvent(sb, ev[0], 0);

    // ---- Init (A: feat0 chain; B: feat1 chain + weight prep) ----
    build_valid<<<1, 32, 0, sa>>>(mask0, vt0, cm0, nv0);
    copy_kernel<<<2048, 256, 0, sa>>>(feat0, x0, NTOK * CDIM);
    gather_split<<<1024, 256, 0, sa>>>(feat0, vt0, nv0, x0h, x0l);
    classify_kernel<<<NTOK / 8, 256, 0, sa>>>(f0wp, proto, f0p, cls0f, c0);
    build_list<<<BATCH * NPROT, 32, 0, sa>>>(c0, mask0, cm0, l0, n0);

    build_valid<<<1, 32, 0, sb>>>(mask1, vt1, cm1, nv1);
    copy_kernel<<<2048, 256, 0, sb>>>(feat1, x1, NTOK * CDIM);
    gather_split<<<1024, 256, 0, sb>>>(feat1, vt1, nv1, x1h, x1l);
    copy_kernel<<<8, 256, 0, sb>>>(proto, protoO, NPROT * CDIM);
    classify_kernel<<<NTOK / 8, 256, 0, sb>>>(f1wp, proto, f1p, cls1f, c1);
    build_list<<<BATCH * NPROT, 32, 0, sb>>>(c1, mask1, cm1, l1, n1);
    for (int i = 0; i < NLAYER; i++) {
        __half* hb = wh + (size_t)i * WLSZ;
        prep_w<<<(65536 + 255) / 256, 256, 0, sb>>>(Wq + (size_t)i * 65536, 256, 256, hb + WOFF_QKV);
        prep_w<<<(65536 + 255) / 256, 256, 0, sb>>>(Wk + (size_t)i * 65536, 256, 256, hb + WOFF_QKV + 256 * 256);
        prep_w<<<(65536 + 255) / 256, 256, 0, sb>>>(Wv + (size_t)i * 65536, 256, 256, hb + WOFF_QKV + 512 * 256);
        prep_w<<<(65536 + 255) / 256, 256, 0, sb>>>(Wm + (size_t)i * 65536, 256, 256, hb + WOFF_M);
        prep_w<<<(262144 + 255) / 256, 256, 0, sb>>>(W1 + (size_t)i * 262144, 512, 512, hb + WOFF_1);
        prep_w<<<(131072 + 255) / 256, 256, 0, sb>>>(W2 + (size_t)i * 131072, 512, 256, hb + WOFF_2);
    }
    cudaEventRecord(ev[1], sb);
    cudaStreamWaitEvent(sa, ev[1], 0);
    cudaEventRecord(ev[9], sa);           // A init (lists/compaction) done
    cudaStreamWaitEvent(sb, ev[9], 0);    // B may read set-0 lists in cross layers

    const __half* wl0 = wh;
    const __half* wl1 = wh + (size_t)1 * WLSZ;
    const __half* wl2 = wh + (size_t)2 * WLSZ;
    const __half* wl3 = wh + (size_t)3 * WLSZ;

    // ---- L0: self-self (concurrent) ----
    run_layer(sa, MODE_SELF, x0, x0h, x0l, x0h, x0l, l0, n0, l0, n0, nv0, nv0, vt0,
              wl0, G1, B1p, G2, B2p, BA, nullptr);
    run_layer(sb, MODE_SELF, x1, x1h, x1l, x1h, x1l, l1, n1, l1, n1, nv1, nv1, vt1,
              wl0, G1, B1p, G2, B2p, BB, nullptr);
    cudaEventRecord(ev[2], sb);
    cudaStreamWaitEvent(sa, ev[2], 0);

    // ---- L1: cross (app1 on A; app2-q overlapped on B) ----
    launch_q(sb, x1h, x1l, wl1, BB, nv1);
    run_layer(sa, MODE_CROSS, x0, x0h, x0l, x1h, x1l, l0, n0, l1, n1, nv0, nv1, vt0,
              wl1, G1 + CDIM, B1p + CDIM, G2 + CDIM, B2p + CDIM, BA, nullptr);
    cudaEventRecord(ev[3], sa);
    cudaStreamWaitEvent(sb, ev[3], 0);
    run_layer(sb, MODE_KVONLY, x1, x1h, x1l, x0h, x0l, l1, n1, l0, n0, nv1, nv0, vt1,
              wl1, G1 + CDIM, B1p + CDIM, G2 + CDIM, B2p + CDIM, BB, ev[4]);
    cudaStreamWaitEvent(sa, ev[4], 0);

    // ---- L2: self-self (concurrent) ----
    run_layer(sa, MODE_SELF, x0, x0h, x0l, x0h, x0l, l0, n0, l0, n0, nv0, nv0, vt0,
              wl2, G1 + 2 * CDIM, B1p + 2 * CDIM, G2 + 2 * CDIM, B2p + 2 * CDIM, BA, nullptr);
    run_layer(sb, MODE_SELF, x1, x1h, x1l, x1h, x1l, l1, n1, l1, n1, nv1, nv1, vt1,
              wl2, G1 + 2 * CDIM, B1p + 2 * CDIM, G2 + 2 * CDIM, B2p + 2 * CDIM, BB, nullptr);
    cudaEventRecord(ev[5], sb);
    cudaStreamWaitEvent(sa, ev[5], 0);

    // ---- L3: cross ----
    launch_q(sb, x1h, x1l, wl3, BB, nv1);
    run_layer(sa, MODE_CROSS, x0, x0h, x0l, x1h, x1l, l0, n0, l1, n1, nv0, nv1, vt0,
              wl3, G1 + 3 * CDIM, B1p + 3 * CDIM, G2 + 3 * CDIM, B2p + 3 * CDIM, BA, nullptr);
    cudaEventRecord(ev[6], sa);
    cudaStreamWaitEvent(sb, ev[6], 0);
    run_layer(sb, MODE_KVONLY, x1, x1h, x1l, x0h, x0l, l1, n1, l0, n0, nv1, nv0, vt1,
              wl3, G1 + 3 * CDIM, B1p + 3 * CDIM, G2 + 3 * CDIM, B2p + 3 * CDIM, BB, nullptr);

    // ---- Join back to default stream ----
    cudaEventRecord(ev[7], sa);
    cudaEventRecord(ev[8], sb);
    cudaStreamWaitEvent(0, ev[7], 0);
    cudaStreamWaitEvent(0, ev[8], 0);

    (void)in_sizes; (void)n_in; (void)out_size;
}